// round 11
// baseline (speedup 1.0000x reference)
#include <cuda_runtime.h>
#include <math.h>

#define N_USER  100000
#define N_ITEM  50000
#define DIM     64
#define N_BEH   3
#define NE      1000000
#define NE_ALL  (N_BEH * NE)
#define BATCH   4096
#define LN_EPS  1e-5f

// Scratch
__device__ float g_S[N_BEH * N_USER];
__device__ float g_A[(size_t)N_BEH * N_ITEM * DIM];
__device__ int   g_mask[N_ITEM];
__device__ int   g_cnt;
__device__ int   g_cu[NE_ALL];
__device__ int   g_cib[NE_ALL];
__device__ float g_cw[NE_ALL];

// ---------------------------------------------------------------------------
__global__ void zero_small_kernel() {
    int idx = blockIdx.x * blockDim.x + threadIdx.x;
    if (idx == 0) g_cnt = 0;
    for (int i = idx; i < N_BEH * N_USER; i += gridDim.x * blockDim.x)
        g_S[i] = 0.0f;
    for (int i = idx; i < N_ITEM; i += gridDim.x * blockDim.x)
        g_mask[i] = 0;
}

// ---------------------------------------------------------------------------
// Fused: set mask AND zero the 3 A-rows for each pos/neg entry directly.
// ---------------------------------------------------------------------------
__global__ void mask_zero_kernel(const int* __restrict__ pos_items,
                                 const int* __restrict__ neg_items) {
    int idx = blockIdx.x * blockDim.x + threadIdx.x;
    int entry = idx / 48;
    int j     = idx - entry * 48;
    if (entry >= 2 * BATCH) return;
    int item = (entry < BATCH) ? pos_items[entry] : neg_items[entry - BATCH];
    if (j == 0) g_mask[item] = 1;
    int beh = j >> 4;
    int q   = j & 15;
    float4* dst = (float4*)&g_A[((size_t)beh * N_ITEM + item) * DIM] + q;
    *dst = make_float4(0.f, 0.f, 0.f, 0.f);
}

// ---------------------------------------------------------------------------
// 256-bit load helper (sm_100a): 8 consecutive floats, 32B-aligned.
// ---------------------------------------------------------------------------
__device__ __forceinline__ void ldg_v8(const float* p, float* r) {
    asm volatile("ld.global.v8.f32 {%0,%1,%2,%3,%4,%5,%6,%7}, [%8];"
                 : "=f"(r[0]), "=f"(r[1]), "=f"(r[2]), "=f"(r[3]),
                   "=f"(r[4]), "=f"(r[5]), "=f"(r[6]), "=f"(r[7])
                 : "l"(p));
}

// ---------------------------------------------------------------------------
// Pass A v8: 8 lanes/edge, 4 edges/warp, ONE v8 load per operand per thread.
// Halves register pressure (uv[8]/iv[8]) -> 100% occupancy ceiling to hide
// the L2 gather latency. Wavefronts unchanged (still ~4 lines/edge floor).
// ---------------------------------------------------------------------------
__global__ __launch_bounds__(256, 8)
void edge_act_kernel(const float* __restrict__ user_emb,
                     const float* __restrict__ item_emb,
                     const float* __restrict__ alpha_w,
                     const float* __restrict__ alpha_b,
                     const int*   __restrict__ edge_index,
                     float* __restrict__ tpw,
                     float* __restrict__ aux) {
    __shared__ float s_aw[64];
    __shared__ float s_ab;

    const unsigned FULL = 0xffffffffu;
    int tid  = threadIdx.x;
    int lane = tid & 31;
    int sl   = lane & 7;                 // sub-lane within edge (0..7)
    size_t e = ((size_t)blockIdx.x * blockDim.x + tid) >> 3;   // edge id
    int b    = (int)(e / NE);            // uniform per block (32 edges/block)
    int el   = (int)(e - (size_t)b * NE);

    if (tid < 64) s_aw[tid] = alpha_w[b * 64 + tid];
    if (tid == 64) s_ab = alpha_b[b];
    __syncthreads();

    const int* ei = edge_index + (size_t)b * 2 * NE;
    int u = ei[el];
    int i = ei[NE + el];

    // lane sl covers floats [sl*8, sl*8+8) of the 64-float row
    const float* up = &user_emb[(size_t)u * (N_BEH * DIM) + b * DIM + sl * 8];
    const float* ip = &item_emb[(size_t)i * (N_BEH * DIM) + b * DIM + sl * 8];

    float uv[8], iv[8];
    ldg_v8(up, uv);
    ldg_v8(ip, iv);

    const float4* a4 = (const float4*)&s_aw[sl * 8];
    float av[8];
    *(float4*)&av[0] = a4[0];
    *(float4*)&av[4] = a4[1];

    float z = 0.f, a2 = 0.f;
    #pragma unroll
    for (int k = 0; k < 8; k++) {
        float d = fabsf(uv[k] - iv[k]);
        z  += d * av[k];
        a2 += d * d;
    }

    #pragma unroll
    for (int o = 4; o; o >>= 1) {
        z  += __shfl_xor_sync(FULL, z,  o);
        a2 += __shfl_xor_sync(FULL, a2, o);
    }

    z += s_ab;
    float act = (z > 0.0f) ? z : (__expf(z) - 1.0f);   // elu(alpha=1)
    float ev  = __expf(act);                            // bounded; no max shift
    if (sl == 0) {
        tpw[(size_t)b * NE + el] = ev;
        aux[(size_t)b * NE + el] = a2;
        float* dst = &g_S[b * N_USER + u];
        asm volatile("red.global.add.f32 [%0], %1;" :: "l"(dst), "f"(ev) : "memory");
    }
}

// ---------------------------------------------------------------------------
// Invert S in place (one rcp per user instead of one div per edge).
// ---------------------------------------------------------------------------
__global__ void rcp_S_kernel() {
    int i = blockIdx.x * blockDim.x + threadIdx.x;
    if (i < N_BEH * N_USER) g_S[i] = __frcp_rn(g_S[i]);
}

// ---------------------------------------------------------------------------
// Normalize tpw (multiply by precomputed 1/S) + compact masked edges.
// ---------------------------------------------------------------------------
__global__ void norm_compact_kernel(const int* __restrict__ edge_index,
                                    float* __restrict__ tpw) {
    const unsigned FULL = 0xffffffffu;
    int t4 = blockIdx.x * blockDim.x + threadIdx.x;
    int idx = t4 * 4;
    bool valid = (idx < NE_ALL);

    int b = 0, e = 0;
    int4 uu = make_int4(0, 0, 0, 0), ii = make_int4(0, 0, 0, 0);
    float4 w = make_float4(0.f, 0.f, 0.f, 0.f);
    int m0 = 0, m1 = 0, m2 = 0, m3 = 0;

    if (valid) {
        b = idx / NE;
        e = idx - b * NE;
        const int* ei = edge_index + (size_t)b * 2 * NE;
        uu = *(const int4*)&ei[e];
        ii = *(const int4*)&ei[NE + e];
        float4 tv = *(const float4*)&tpw[idx];
        const float* Sb = &g_S[b * N_USER];     // holds 1/S
        w.x = tv.x * Sb[uu.x];
        w.y = tv.y * Sb[uu.y];
        w.z = tv.z * Sb[uu.z];
        w.w = tv.w * Sb[uu.w];
        *(float4*)&tpw[idx] = w;
        m0 = g_mask[ii.x]; m1 = g_mask[ii.y]; m2 = g_mask[ii.z]; m3 = g_mask[ii.w];
    }
    int cnt = m0 + m1 + m2 + m3;

    int lane = threadIdx.x & 31;
    int pre = cnt;
    #pragma unroll
    for (int o = 1; o < 32; o <<= 1) {
        int v = __shfl_up_sync(FULL, pre, o);
        if (lane >= o) pre += v;
    }
    int total = __shfl_sync(FULL, pre, 31);
    int excl  = pre - cnt;
    int base = 0;
    if (lane == 31 && total) base = atomicAdd(&g_cnt, total);
    base = __shfl_sync(FULL, base, 31);

    if (valid && cnt) {
        int off = base + excl;
        int us[4] = {uu.x, uu.y, uu.z, uu.w};
        int is[4] = {ii.x, ii.y, ii.z, ii.w};
        float ws[4] = {w.x, w.y, w.z, w.w};
        int ms[4] = {m0, m1, m2, m3};
        #pragma unroll
        for (int j = 0; j < 4; j++) {
            if (ms[j]) {
                g_cu[off]  = us[j] * (N_BEH * DIM) + b * DIM;
                g_cib[off] = (b * N_ITEM + is[j]) * DIM;
                g_cw[off]  = ws[j];
                off++;
            }
        }
    }
}

// ---------------------------------------------------------------------------
// Dense scatter over compacted list.
// ---------------------------------------------------------------------------
__global__ void scatter2_kernel(const float* __restrict__ user_emb) {
    int l    = threadIdx.x & 15;
    int slot = (blockIdx.x * blockDim.x + threadIdx.x) >> 4;
    int stride = (gridDim.x * blockDim.x) >> 4;
    int total = g_cnt;
    for (int e = slot; e < total; e += stride) {
        int uoff = g_cu[e];
        int aoff = g_cib[e];
        float w  = g_cw[e];
        float4 uv = *(const float4*)&user_emb[(size_t)uoff + 4 * l];
        float* dst = &g_A[(size_t)aoff + 4 * l];
        asm volatile("red.global.add.v4.f32 [%0], {%1,%2,%3,%4};"
                     :: "l"(dst), "f"(w * uv.x), "f"(w * uv.y),
                        "f"(w * uv.z), "f"(w * uv.w) : "memory");
    }
}

// ---------------------------------------------------------------------------
// Pass C: 8 rows/block, 128 threads, 4 rows/thread in matmul phases.
// ---------------------------------------------------------------------------
#define ROWS_PB 8
#define ROW_F   816
// layout per row: xs@0, qs@192(=ao), ks@384(=hh), vs@576, sc@768, mus@804, rss@808

__global__ __launch_bounds__(128)
void attn_kernel(const float* __restrict__ user_emb,
                 const float* __restrict__ item_emb,
                 const float* __restrict__ wq, const float* __restrict__ bq,
                 const float* __restrict__ wk, const float* __restrict__ bk,
                 const float* __restrict__ wv, const float* __restrict__ bv,
                 const float* __restrict__ wo, const float* __restrict__ bo,
                 const float* __restrict__ lng, const float* __restrict__ lnb,
                 const int* __restrict__ users,
                 const int* __restrict__ pos_items,
                 const int* __restrict__ neg_items,
                 float* __restrict__ emb_out) {
    __shared__ float sm[ROWS_PB * ROW_F];
    int t = threadIdx.x & 63;
    int g = threadIdx.x >> 6;
    int row0 = blockIdx.x * ROWS_PB;

    #pragma unroll
    for (int r = 0; r < 4; r++) {
        int lr  = g * 4 + r;
        int row = row0 + lr;
        int node; bool is_user;
        if (row < BATCH)          { node = users[row];                 is_user = true;  }
        else if (row < 2 * BATCH) { node = pos_items[row - BATCH];     is_user = false; }
        else                      { node = neg_items[row - 2 * BATCH]; is_user = false; }
        float* xs = sm + lr * ROW_F;
        #pragma unroll
        for (int beh = 0; beh < 3; beh++) {
            float v;
            if (is_user) {
                v = user_emb[(size_t)node * (N_BEH * DIM) + beh * DIM + t];
            } else {
                v = 2.0f * g_A[((size_t)beh * N_ITEM + node) * DIM + t]
                    + item_emb[(size_t)node * (N_BEH * DIM) + beh * DIM + t];
            }
            xs[beh * 64 + t] = v;
        }
    }
    __syncthreads();

    {
        float aq[4][3], ak[4][3], av[4][3];
        float bqv = bq[t], bkv = bk[t], bvv = bv[t];
        #pragma unroll
        for (int r = 0; r < 4; r++)
            #pragma unroll
            for (int beh = 0; beh < 3; beh++) {
                aq[r][beh] = bqv; ak[r][beh] = bkv; av[r][beh] = bvv;
            }
        #pragma unroll 4
        for (int d4 = 0; d4 < 64; d4 += 4) {
            float w1[4], w2[4], w3[4];
            #pragma unroll
            for (int k = 0; k < 4; k++) {
                w1[k] = wq[(d4 + k) * 64 + t];
                w2[k] = wk[(d4 + k) * 64 + t];
                w3[k] = wv[(d4 + k) * 64 + t];
            }
            #pragma unroll
            for (int r = 0; r < 4; r++) {
                const float* xr = sm + (g * 4 + r) * ROW_F;
                #pragma unroll
                for (int beh = 0; beh < 3; beh++) {
                    float4 x = *(const float4*)&xr[beh * 64 + d4];
                    aq[r][beh] += x.x * w1[0] + x.y * w1[1] + x.z * w1[2] + x.w * w1[3];
                    ak[r][beh] += x.x * w2[0] + x.y * w2[1] + x.z * w2[2] + x.w * w2[3];
                    av[r][beh] += x.x * w3[0] + x.y * w3[1] + x.z * w3[2] + x.w * w3[3];
                }
            }
        }
        #pragma unroll
        for (int r = 0; r < 4; r++) {
            float* base = sm + (g * 4 + r) * ROW_F;
            #pragma unroll
            for (int beh = 0; beh < 3; beh++) {
                base[192 + beh * 64 + t] = aq[r][beh];
                base[384 + beh * 64 + t] = ak[r][beh];
                base[576 + beh * 64 + t] = av[r][beh];
            }
        }
    }
    __syncthreads();

    for (int uu = threadIdx.x; uu < ROWS_PB * 36; uu += 128) {
        int lr  = uu / 36;
        int rem = uu - lr * 36;
        int h   = rem / 9;
        int qb  = (rem % 9) / 3;
        int kb  = rem % 3;
        float* base = sm + lr * ROW_F;
        float s = 0.0f;
        #pragma unroll
        for (int j = 0; j < 16; j++)
            s += base[192 + qb * 64 + h * 16 + j] * base[384 + kb * 64 + h * 16 + j];
        base[768 + rem] = s * 0.25f;
    }
    __syncthreads();

    if (threadIdx.x < ROWS_PB * 12) {
        int lr = threadIdx.x / 12;
        int p  = threadIdx.x - lr * 12;
        float* sc = sm + lr * ROW_F + 768 + p * 3;
        float s0 = sc[0], s1 = sc[1], s2 = sc[2];
        float m = fmaxf(s0, fmaxf(s1, s2));
        float e0 = expf(s0 - m), e1 = expf(s1 - m), e2 = expf(s2 - m);
        float inv = 1.0f / (e0 + e1 + e2);
        sc[0] = e0 * inv; sc[1] = e1 * inv; sc[2] = e2 * inv;
    }
    __syncthreads();

    for (int uu = threadIdx.x; uu < ROWS_PB * 64; uu += 128) {
        int lr = uu >> 6;
        int tt = uu & 63;
        int h  = tt >> 4;
        float* base = sm + lr * ROW_F;
        #pragma unroll
        for (int qb = 0; qb < 3; qb++) {
            float a = 0.0f;
            #pragma unroll
            for (int kb = 0; kb < 3; kb++)
                a += base[768 + h * 9 + qb * 3 + kb] * base[576 + kb * 64 + tt];
            base[192 + qb * 64 + tt] = a;
        }
    }
    __syncthreads();

    {
        float acc[4][3];
        float bov = bo[t];
        #pragma unroll
        for (int r = 0; r < 4; r++)
            #pragma unroll
            for (int beh = 0; beh < 3; beh++) acc[r][beh] = bov;
        #pragma unroll 4
        for (int d4 = 0; d4 < 64; d4 += 4) {
            float w[4];
            #pragma unroll
            for (int k = 0; k < 4; k++) w[k] = wo[(d4 + k) * 64 + t];
            #pragma unroll
            for (int r = 0; r < 4; r++) {
                const float* base = sm + (g * 4 + r) * ROW_F;
                #pragma unroll
                for (int beh = 0; beh < 3; beh++) {
                    float4 a = *(const float4*)&base[192 + beh * 64 + d4];
                    acc[r][beh] += a.x * w[0] + a.y * w[1] + a.z * w[2] + a.w * w[3];
                }
            }
        }
        __syncthreads();
        #pragma unroll
        for (int r = 0; r < 4; r++) {
            float* base = sm + (g * 4 + r) * ROW_F;
            #pragma unroll
            for (int beh = 0; beh < 3; beh++)
                base[384 + beh * 64 + t] = acc[r][beh] + base[beh * 64 + t];
        }
    }
    __syncthreads();

    if (threadIdx.x < ROWS_PB * 3) {
        int lr  = threadIdx.x / 3;
        int beh = threadIdx.x - lr * 3;
        float* hh = sm + lr * ROW_F + 384 + beh * 64;
        float s = 0.0f;
        #pragma unroll 8
        for (int j = 0; j < 64; j++) s += hh[j];
        float mu = s * (1.0f / 64.0f);
        float v = 0.0f;
        #pragma unroll 8
        for (int j = 0; j < 64; j++) {
            float dd = hh[j] - mu;
            v += dd * dd;
        }
        v *= (1.0f / 64.0f);
        sm[lr * ROW_F + 804 + beh] = mu;
        sm[lr * ROW_F + 808 + beh] = rsqrtf(v + LN_EPS);
    }
    __syncthreads();

    for (int uu = threadIdx.x; uu < ROWS_PB * 64; uu += 128) {
        int lr = uu >> 6;
        int tt = uu & 63;
        float* base = sm + lr * ROW_F;
        float gg = lng[tt], bb = lnb[tt];
        float gsum = 0.0f;
        #pragma unroll
        for (int beh = 0; beh < 3; beh++)
            gsum += (base[384 + beh * 64 + tt] - base[804 + beh]) * base[808 + beh] * gg + bb;
        emb_out[(size_t)(row0 + lr) * 64 + tt] = gsum;
    }
}

// ---------------------------------------------------------------------------
extern "C" void kernel_launch(void* const* d_in, const int* in_sizes, int n_in,
                              void* d_out, int out_size) {
    const float* user_emb = (const float*)d_in[0];
    const float* item_emb = (const float*)d_in[1];
    const float* alpha_w  = (const float*)d_in[2];
    const float* alpha_b  = (const float*)d_in[3];
    const float* wq = (const float*)d_in[4];
    const float* bq = (const float*)d_in[5];
    const float* wk = (const float*)d_in[6];
    const float* bk = (const float*)d_in[7];
    const float* wv = (const float*)d_in[8];
    const float* bv = (const float*)d_in[9];
    const float* wo = (const float*)d_in[10];
    const float* bo = (const float*)d_in[11];
    const float* lng = (const float*)d_in[12];
    const float* lnb = (const float*)d_in[13];
    const int* edge_index = (const int*)d_in[14];
    const int* users      = (const int*)d_in[15];
    const int* pos_items  = (const int*)d_in[16];
    const int* neg_items  = (const int*)d_in[17];

    float* out     = (float*)d_out;
    float* emb_out = out;
    float* tpw     = out + (size_t)3 * BATCH * DIM;
    float* aux     = tpw + (size_t)N_BEH * NE;

    zero_small_kernel<<<256, 256>>>();
    mask_zero_kernel<<<(2 * BATCH * 48 + 255) / 256, 256>>>(pos_items, neg_items);

    // Pass A: 3M edges * 8 lanes / 256 (exact: 93750 blocks)
    edge_act_kernel<<<(size_t)NE_ALL * 8 / 256, 256>>>(user_emb, item_emb,
                                                       alpha_w, alpha_b,
                                                       edge_index, tpw, aux);

    rcp_S_kernel<<<(N_BEH * N_USER + 255) / 256, 256>>>();

    norm_compact_kernel<<<(NE_ALL / 4 + 255) / 256, 256>>>(edge_index, tpw);

    scatter2_kernel<<<4096, 256>>>(user_emb);

    attn_kernel<<<(3 * BATCH) / ROWS_PB, 128>>>(user_emb, item_emb,
                                                wq, bq, wk, bk, wv, bv, wo, bo,
                                                lng, lnb, users, pos_items, neg_items,
                                                emb_out);
}

// round 12
// speedup vs baseline: 1.2641x; 1.2641x over previous
#include <cuda_runtime.h>
#include <math.h>

#define N_USER  100000
#define N_ITEM  50000
#define DIM     64
#define N_BEH   3
#define NE      1000000
#define NE_ALL  (N_BEH * NE)
#define BATCH   4096
#define LN_EPS  1e-5f

// Scratch
__device__ float g_S[N_BEH * N_USER];
__device__ float g_A[(size_t)N_BEH * N_ITEM * DIM];
__device__ int   g_mask[N_ITEM];
__device__ int   g_cnt;
__device__ int   g_cu[NE_ALL];
__device__ int   g_cib[NE_ALL];
__device__ float g_cw[NE_ALL];

// ---------------------------------------------------------------------------
// Fused init: zero S + mask + counter, set mask from pos/neg, zero A rows.
// Grid sized to cover max(S+mask scan, 2*BATCH*48 A-zeroing).
// ---------------------------------------------------------------------------
__global__ void init_kernel(const int* __restrict__ pos_items,
                            const int* __restrict__ neg_items) {
    int idx = blockIdx.x * blockDim.x + threadIdx.x;
    int nthreads = gridDim.x * blockDim.x;
    if (idx == 0) g_cnt = 0;
    for (int i = idx; i < N_BEH * N_USER; i += nthreads)
        g_S[i] = 0.0f;
    for (int i = idx; i < N_ITEM; i += nthreads)
        g_mask[i] = 0;
    // NOTE: mask writes below race with the zeroing above only if the same
    // thread grid interleaves — avoided by doing mask set in a second kernel.
}

__global__ void mask_zero_kernel(const int* __restrict__ pos_items,
                                 const int* __restrict__ neg_items) {
    int idx = blockIdx.x * blockDim.x + threadIdx.x;
    int entry = idx / 48;
    int j     = idx - entry * 48;
    if (entry >= 2 * BATCH) return;
    int item = (entry < BATCH) ? pos_items[entry] : neg_items[entry - BATCH];
    if (j == 0) g_mask[item] = 1;
    int beh = j >> 4;
    int q   = j & 15;
    float4* dst = (float4*)&g_A[((size_t)beh * N_ITEM + item) * DIM] + q;
    *dst = make_float4(0.f, 0.f, 0.f, 0.f);
}

// ---------------------------------------------------------------------------
// 256-bit load helper (sm_100a): 8 consecutive floats, 32B-aligned.
// ---------------------------------------------------------------------------
__device__ __forceinline__ void ldg_v8(const float* p, float* r) {
    asm volatile("ld.global.v8.f32 {%0,%1,%2,%3,%4,%5,%6,%7}, [%8];"
                 : "=f"(r[0]), "=f"(r[1]), "=f"(r[2]), "=f"(r[3]),
                   "=f"(r[4]), "=f"(r[5]), "=f"(r[6]), "=f"(r[7])
                 : "l"(p));
}

// ---------------------------------------------------------------------------
// Pass A (v7, proven 144us config): 4 lanes/edge, 8 edges/warp,
// line-aligned v8 loads, smem alpha, fast __expf.
// __launch_bounds__(256,7): regs capped at 36 -> 7 blocks/SM (56 warps).
// ---------------------------------------------------------------------------
__global__ __launch_bounds__(256, 7)
void edge_act_kernel(const float* __restrict__ user_emb,
                     const float* __restrict__ item_emb,
                     const float* __restrict__ alpha_w,
                     const float* __restrict__ alpha_b,
                     const int*   __restrict__ edge_index,
                     float* __restrict__ tpw,
                     float* __restrict__ aux) {
    __shared__ float s_aw[64];
    __shared__ float s_ab;

    const unsigned FULL = 0xffffffffu;
    int tid  = threadIdx.x;
    int lane = tid & 31;
    int sl   = lane & 3;
    size_t e = ((size_t)blockIdx.x * blockDim.x + tid) >> 2;
    int b    = (int)(e / NE);            // uniform per block
    int el   = (int)(e - (size_t)b * NE);

    if (tid < 64) s_aw[tid] = alpha_w[b * 64 + tid];
    if (tid == 64) s_ab = alpha_b[b];
    __syncthreads();

    const int* ei = edge_index + (size_t)b * 2 * NE;
    int u = ei[el];
    int i = ei[NE + el];

    // line-aligned: lane sl covers floats [sl*8, sl*8+8) and [32+sl*8, +8)
    const float* up = &user_emb[(size_t)u * (N_BEH * DIM) + b * DIM + sl * 8];
    const float* ip = &item_emb[(size_t)i * (N_BEH * DIM) + b * DIM + sl * 8];

    float uv[16], iv[16];
    ldg_v8(up,      uv);
    ldg_v8(ip,      iv);
    ldg_v8(up + 32, uv + 8);
    ldg_v8(ip + 32, iv + 8);

    const float4* a4lo = (const float4*)&s_aw[sl * 8];
    const float4* a4hi = (const float4*)&s_aw[32 + sl * 8];
    float av[16];
    *(float4*)&av[0]  = a4lo[0];
    *(float4*)&av[4]  = a4lo[1];
    *(float4*)&av[8]  = a4hi[0];
    *(float4*)&av[12] = a4hi[1];

    float z = 0.f, a2 = 0.f;
    #pragma unroll
    for (int k = 0; k < 16; k++) {
        float d = fabsf(uv[k] - iv[k]);
        z  += d * av[k];
        a2 += d * d;
    }

    #pragma unroll
    for (int o = 2; o; o >>= 1) {
        z  += __shfl_xor_sync(FULL, z,  o);
        a2 += __shfl_xor_sync(FULL, a2, o);
    }

    z += s_ab;
    float act = (z > 0.0f) ? z : (__expf(z) - 1.0f);   // elu(alpha=1)
    float ev  = __expf(act);                            // bounded; no max shift
    if (sl == 0) {
        tpw[(size_t)b * NE + el] = ev;
        aux[(size_t)b * NE + el] = a2;
        float* dst = &g_S[b * N_USER + u];
        asm volatile("red.global.add.f32 [%0], %1;" :: "l"(dst), "f"(ev) : "memory");
    }
}

// ---------------------------------------------------------------------------
// Invert S in place.
// ---------------------------------------------------------------------------
__global__ void rcp_S_kernel() {
    int i = blockIdx.x * blockDim.x + threadIdx.x;
    if (i < N_BEH * N_USER) g_S[i] = __frcp_rn(g_S[i]);
}

// ---------------------------------------------------------------------------
// Normalize tpw (multiply by precomputed 1/S) + compact masked edges.
// ---------------------------------------------------------------------------
__global__ void norm_compact_kernel(const int* __restrict__ edge_index,
                                    float* __restrict__ tpw) {
    const unsigned FULL = 0xffffffffu;
    int t4 = blockIdx.x * blockDim.x + threadIdx.x;
    int idx = t4 * 4;
    bool valid = (idx < NE_ALL);

    int b = 0, e = 0;
    int4 uu = make_int4(0, 0, 0, 0), ii = make_int4(0, 0, 0, 0);
    float4 w = make_float4(0.f, 0.f, 0.f, 0.f);
    int m0 = 0, m1 = 0, m2 = 0, m3 = 0;

    if (valid) {
        b = idx / NE;
        e = idx - b * NE;
        const int* ei = edge_index + (size_t)b * 2 * NE;
        uu = *(const int4*)&ei[e];
        ii = *(const int4*)&ei[NE + e];
        float4 tv = *(const float4*)&tpw[idx];
        const float* Sb = &g_S[b * N_USER];     // holds 1/S
        w.x = tv.x * Sb[uu.x];
        w.y = tv.y * Sb[uu.y];
        w.z = tv.z * Sb[uu.z];
        w.w = tv.w * Sb[uu.w];
        *(float4*)&tpw[idx] = w;
        m0 = g_mask[ii.x]; m1 = g_mask[ii.y]; m2 = g_mask[ii.z]; m3 = g_mask[ii.w];
    }
    int cnt = m0 + m1 + m2 + m3;

    int lane = threadIdx.x & 31;
    int pre = cnt;
    #pragma unroll
    for (int o = 1; o < 32; o <<= 1) {
        int v = __shfl_up_sync(FULL, pre, o);
        if (lane >= o) pre += v;
    }
    int total = __shfl_sync(FULL, pre, 31);
    int excl  = pre - cnt;
    int base = 0;
    if (lane == 31 && total) base = atomicAdd(&g_cnt, total);
    base = __shfl_sync(FULL, base, 31);

    if (valid && cnt) {
        int off = base + excl;
        int us[4] = {uu.x, uu.y, uu.z, uu.w};
        int is[4] = {ii.x, ii.y, ii.z, ii.w};
        float ws[4] = {w.x, w.y, w.z, w.w};
        int ms[4] = {m0, m1, m2, m3};
        #pragma unroll
        for (int j = 0; j < 4; j++) {
            if (ms[j]) {
                g_cu[off]  = us[j] * (N_BEH * DIM) + b * DIM;
                g_cib[off] = (b * N_ITEM + is[j]) * DIM;
                g_cw[off]  = ws[j];
                off++;
            }
        }
    }
}

// ---------------------------------------------------------------------------
// Dense scatter over compacted list.
// ---------------------------------------------------------------------------
__global__ void scatter2_kernel(const float* __restrict__ user_emb) {
    int l    = threadIdx.x & 15;
    int slot = (blockIdx.x * blockDim.x + threadIdx.x) >> 4;
    int stride = (gridDim.x * blockDim.x) >> 4;
    int total = g_cnt;
    for (int e = slot; e < total; e += stride) {
        int uoff = g_cu[e];
        int aoff = g_cib[e];
        float w  = g_cw[e];
        float4 uv = *(const float4*)&user_emb[(size_t)uoff + 4 * l];
        float* dst = &g_A[(size_t)aoff + 4 * l];
        asm volatile("red.global.add.v4.f32 [%0], {%1,%2,%3,%4};"
                     :: "l"(dst), "f"(w * uv.x), "f"(w * uv.y),
                        "f"(w * uv.z), "f"(w * uv.w) : "memory");
    }
}

// ---------------------------------------------------------------------------
// Pass C: 8 rows/block, 128 threads, 4 rows/thread in matmul phases.
// ---------------------------------------------------------------------------
#define ROWS_PB 8
#define ROW_F   816
// layout per row: xs@0, qs@192(=ao), ks@384(=hh), vs@576, sc@768, mus@804, rss@808

__global__ __launch_bounds__(128)
void attn_kernel(const float* __restrict__ user_emb,
                 const float* __restrict__ item_emb,
                 const float* __restrict__ wq, const float* __restrict__ bq,
                 const float* __restrict__ wk, const float* __restrict__ bk,
                 const float* __restrict__ wv, const float* __restrict__ bv,
                 const float* __restrict__ wo, const float* __restrict__ bo,
                 const float* __restrict__ lng, const float* __restrict__ lnb,
                 const int* __restrict__ users,
                 const int* __restrict__ pos_items,
                 const int* __restrict__ neg_items,
                 float* __restrict__ emb_out) {
    __shared__ float sm[ROWS_PB * ROW_F];
    int t = threadIdx.x & 63;
    int g = threadIdx.x >> 6;
    int row0 = blockIdx.x * ROWS_PB;

    #pragma unroll
    for (int r = 0; r < 4; r++) {
        int lr  = g * 4 + r;
        int row = row0 + lr;
        int node; bool is_user;
        if (row < BATCH)          { node = users[row];                 is_user = true;  }
        else if (row < 2 * BATCH) { node = pos_items[row - BATCH];     is_user = false; }
        else                      { node = neg_items[row - 2 * BATCH]; is_user = false; }
        float* xs = sm + lr * ROW_F;
        #pragma unroll
        for (int beh = 0; beh < 3; beh++) {
            float v;
            if (is_user) {
                v = user_emb[(size_t)node * (N_BEH * DIM) + beh * DIM + t];
            } else {
                v = 2.0f * g_A[((size_t)beh * N_ITEM + node) * DIM + t]
                    + item_emb[(size_t)node * (N_BEH * DIM) + beh * DIM + t];
            }
            xs[beh * 64 + t] = v;
        }
    }
    __syncthreads();

    {
        float aq[4][3], ak[4][3], av[4][3];
        float bqv = bq[t], bkv = bk[t], bvv = bv[t];
        #pragma unroll
        for (int r = 0; r < 4; r++)
            #pragma unroll
            for (int beh = 0; beh < 3; beh++) {
                aq[r][beh] = bqv; ak[r][beh] = bkv; av[r][beh] = bvv;
            }
        #pragma unroll 4
        for (int d4 = 0; d4 < 64; d4 += 4) {
            float w1[4], w2[4], w3[4];
            #pragma unroll
            for (int k = 0; k < 4; k++) {
                w1[k] = wq[(d4 + k) * 64 + t];
                w2[k] = wk[(d4 + k) * 64 + t];
                w3[k] = wv[(d4 + k) * 64 + t];
            }
            #pragma unroll
            for (int r = 0; r < 4; r++) {
                const float* xr = sm + (g * 4 + r) * ROW_F;
                #pragma unroll
                for (int beh = 0; beh < 3; beh++) {
                    float4 x = *(const float4*)&xr[beh * 64 + d4];
                    aq[r][beh] += x.x * w1[0] + x.y * w1[1] + x.z * w1[2] + x.w * w1[3];
                    ak[r][beh] += x.x * w2[0] + x.y * w2[1] + x.z * w2[2] + x.w * w2[3];
                    av[r][beh] += x.x * w3[0] + x.y * w3[1] + x.z * w3[2] + x.w * w3[3];
                }
            }
        }
        #pragma unroll
        for (int r = 0; r < 4; r++) {
            float* base = sm + (g * 4 + r) * ROW_F;
            #pragma unroll
            for (int beh = 0; beh < 3; beh++) {
                base[192 + beh * 64 + t] = aq[r][beh];
                base[384 + beh * 64 + t] = ak[r][beh];
                base[576 + beh * 64 + t] = av[r][beh];
            }
        }
    }
    __syncthreads();

    for (int uu = threadIdx.x; uu < ROWS_PB * 36; uu += 128) {
        int lr  = uu / 36;
        int rem = uu - lr * 36;
        int h   = rem / 9;
        int qb  = (rem % 9) / 3;
        int kb  = rem % 3;
        float* base = sm + lr * ROW_F;
        float s = 0.0f;
        #pragma unroll
        for (int j = 0; j < 16; j++)
            s += base[192 + qb * 64 + h * 16 + j] * base[384 + kb * 64 + h * 16 + j];
        base[768 + rem] = s * 0.25f;
    }
    __syncthreads();

    if (threadIdx.x < ROWS_PB * 12) {
        int lr = threadIdx.x / 12;
        int p  = threadIdx.x - lr * 12;
        float* sc = sm + lr * ROW_F + 768 + p * 3;
        float s0 = sc[0], s1 = sc[1], s2 = sc[2];
        float m = fmaxf(s0, fmaxf(s1, s2));
        float e0 = expf(s0 - m), e1 = expf(s1 - m), e2 = expf(s2 - m);
        float inv = 1.0f / (e0 + e1 + e2);
        sc[0] = e0 * inv; sc[1] = e1 * inv; sc[2] = e2 * inv;
    }
    __syncthreads();

    for (int uu = threadIdx.x; uu < ROWS_PB * 64; uu += 128) {
        int lr = uu >> 6;
        int tt = uu & 63;
        int h  = tt >> 4;
        float* base = sm + lr * ROW_F;
        #pragma unroll
        for (int qb = 0; qb < 3; qb++) {
            float a = 0.0f;
            #pragma unroll
            for (int kb = 0; kb < 3; kb++)
                a += base[768 + h * 9 + qb * 3 + kb] * base[576 + kb * 64 + tt];
            base[192 + qb * 64 + tt] = a;
        }
    }
    __syncthreads();

    {
        float acc[4][3];
        float bov = bo[t];
        #pragma unroll
        for (int r = 0; r < 4; r++)
            #pragma unroll
            for (int beh = 0; beh < 3; beh++) acc[r][beh] = bov;
        #pragma unroll 4
        for (int d4 = 0; d4 < 64; d4 += 4) {
            float w[4];
            #pragma unroll
            for (int k = 0; k < 4; k++) w[k] = wo[(d4 + k) * 64 + t];
            #pragma unroll
            for (int r = 0; r < 4; r++) {
                const float* base = sm + (g * 4 + r) * ROW_F;
                #pragma unroll
                for (int beh = 0; beh < 3; beh++) {
                    float4 a = *(const float4*)&base[192 + beh * 64 + d4];
                    acc[r][beh] += a.x * w[0] + a.y * w[1] + a.z * w[2] + a.w * w[3];
                }
            }
        }
        __syncthreads();
        #pragma unroll
        for (int r = 0; r < 4; r++) {
            float* base = sm + (g * 4 + r) * ROW_F;
            #pragma unroll
            for (int beh = 0; beh < 3; beh++)
                base[384 + beh * 64 + t] = acc[r][beh] + base[beh * 64 + t];
        }
    }
    __syncthreads();

    if (threadIdx.x < ROWS_PB * 3) {
        int lr  = threadIdx.x / 3;
        int beh = threadIdx.x - lr * 3;
        float* hh = sm + lr * ROW_F + 384 + beh * 64;
        float s = 0.0f;
        #pragma unroll 8
        for (int j = 0; j < 64; j++) s += hh[j];
        float mu = s * (1.0f / 64.0f);
        float v = 0.0f;
        #pragma unroll 8
        for (int j = 0; j < 64; j++) {
            float dd = hh[j] - mu;
            v += dd * dd;
        }
        v *= (1.0f / 64.0f);
        sm[lr * ROW_F + 804 + beh] = mu;
        sm[lr * ROW_F + 808 + beh] = rsqrtf(v + LN_EPS);
    }
    __syncthreads();

    for (int uu = threadIdx.x; uu < ROWS_PB * 64; uu += 128) {
        int lr = uu >> 6;
        int tt = uu & 63;
        float* base = sm + lr * ROW_F;
        float gg = lng[tt], bb = lnb[tt];
        float gsum = 0.0f;
        #pragma unroll
        for (int beh = 0; beh < 3; beh++)
            gsum += (base[384 + beh * 64 + tt] - base[804 + beh]) * base[808 + beh] * gg + bb;
        emb_out[(size_t)(row0 + lr) * 64 + tt] = gsum;
    }
}

// ---------------------------------------------------------------------------
extern "C" void kernel_launch(void* const* d_in, const int* in_sizes, int n_in,
                              void* d_out, int out_size) {
    const float* user_emb = (const float*)d_in[0];
    const float* item_emb = (const float*)d_in[1];
    const float* alpha_w  = (const float*)d_in[2];
    const float* alpha_b  = (const float*)d_in[3];
    const float* wq = (const float*)d_in[4];
    const float* bq = (const float*)d_in[5];
    const float* wk = (const float*)d_in[6];
    const float* bk = (const float*)d_in[7];
    const float* wv = (const float*)d_in[8];
    const float* bv = (const float*)d_in[9];
    const float* wo = (const float*)d_in[10];
    const float* bo = (const float*)d_in[11];
    const float* lng = (const float*)d_in[12];
    const float* lnb = (const float*)d_in[13];
    const int* edge_index = (const int*)d_in[14];
    const int* users      = (const int*)d_in[15];
    const int* pos_items  = (const int*)d_in[16];
    const int* neg_items  = (const int*)d_in[17];

    float* out     = (float*)d_out;
    float* emb_out = out;
    float* tpw     = out + (size_t)3 * BATCH * DIM;
    float* aux     = tpw + (size_t)N_BEH * NE;

    init_kernel<<<256, 256>>>(pos_items, neg_items);
    mask_zero_kernel<<<(2 * BATCH * 48 + 255) / 256, 256>>>(pos_items, neg_items);

    // Pass A: 3M edges * 4 lanes / 256 (exact: 46875 blocks)
    edge_act_kernel<<<(size_t)NE_ALL * 4 / 256, 256>>>(user_emb, item_emb,
                                                       alpha_w, alpha_b,
                                                       edge_index, tpw, aux);

    rcp_S_kernel<<<(N_BEH * N_USER + 255) / 256, 256>>>();

    norm_compact_kernel<<<(NE_ALL / 4 + 255) / 256, 256>>>(edge_index, tpw);

    scatter2_kernel<<<4096, 256>>>(user_emb);

    attn_kernel<<<(3 * BATCH) / ROWS_PB, 128>>>(user_emb, item_emb,
                                                wq, bq, wk, bk, wv, bv, wo, bo,
                                                lng, lnb, users, pos_items, neg_items,
                                                emb_out);
}

// round 13
// speedup vs baseline: 1.2848x; 1.0164x over previous
#include <cuda_runtime.h>
#include <math.h>

#define N_USER  100000
#define N_ITEM  50000
#define DIM     64
#define N_BEH   3
#define NE      1000000
#define NE_ALL  (N_BEH * NE)
#define BATCH   4096
#define LN_EPS  1e-5f

// Scratch
__device__ float g_S[N_BEH * N_USER];
__device__ float g_A[(size_t)N_BEH * N_ITEM * DIM];
__device__ int   g_mask[N_ITEM];
__device__ int   g_cnt;
__device__ int   g_cu[NE_ALL];
__device__ int   g_cib[NE_ALL];
__device__ float g_cw[NE_ALL];

// ---------------------------------------------------------------------------
__global__ void init_kernel(const int* __restrict__ pos_items,
                            const int* __restrict__ neg_items) {
    int idx = blockIdx.x * blockDim.x + threadIdx.x;
    int nthreads = gridDim.x * blockDim.x;
    if (idx == 0) g_cnt = 0;
    for (int i = idx; i < N_BEH * N_USER; i += nthreads)
        g_S[i] = 0.0f;
    for (int i = idx; i < N_ITEM; i += nthreads)
        g_mask[i] = 0;
}

__global__ void mask_zero_kernel(const int* __restrict__ pos_items,
                                 const int* __restrict__ neg_items) {
    int idx = blockIdx.x * blockDim.x + threadIdx.x;
    int entry = idx / 48;
    int j     = idx - entry * 48;
    if (entry >= 2 * BATCH) return;
    int item = (entry < BATCH) ? pos_items[entry] : neg_items[entry - BATCH];
    if (j == 0) g_mask[item] = 1;
    int beh = j >> 4;
    int q   = j & 15;
    float4* dst = (float4*)&g_A[((size_t)beh * N_ITEM + item) * DIM] + q;
    *dst = make_float4(0.f, 0.f, 0.f, 0.f);
}

// ---------------------------------------------------------------------------
// 256-bit load helper (sm_100a): 8 consecutive floats, 32B-aligned.
// ---------------------------------------------------------------------------
__device__ __forceinline__ void ldg_v8(const float* p, float* r) {
    asm volatile("ld.global.v8.f32 {%0,%1,%2,%3,%4,%5,%6,%7}, [%8];"
                 : "=f"(r[0]), "=f"(r[1]), "=f"(r[2]), "=f"(r[3]),
                   "=f"(r[4]), "=f"(r[5]), "=f"(r[6]), "=f"(r[7])
                 : "l"(p));
}

// ---------------------------------------------------------------------------
// Pass A (v7 proven): 4 lanes/edge, 8 edges/warp, line-aligned v8 loads,
// smem alpha, fast __expf, __launch_bounds__(256,7).
// ---------------------------------------------------------------------------
__global__ __launch_bounds__(256, 7)
void edge_act_kernel(const float* __restrict__ user_emb,
                     const float* __restrict__ item_emb,
                     const float* __restrict__ alpha_w,
                     const float* __restrict__ alpha_b,
                     const int*   __restrict__ edge_index,
                     float* __restrict__ tpw,
                     float* __restrict__ aux) {
    __shared__ float s_aw[64];
    __shared__ float s_ab;

    const unsigned FULL = 0xffffffffu;
    int tid  = threadIdx.x;
    int lane = tid & 31;
    int sl   = lane & 3;
    size_t e = ((size_t)blockIdx.x * blockDim.x + tid) >> 2;
    int b    = (int)(e / NE);            // uniform per block
    int el   = (int)(e - (size_t)b * NE);

    if (tid < 64) s_aw[tid] = alpha_w[b * 64 + tid];
    if (tid == 64) s_ab = alpha_b[b];
    __syncthreads();

    const int* ei = edge_index + (size_t)b * 2 * NE;
    int u = ei[el];
    int i = ei[NE + el];

    const float* up = &user_emb[(size_t)u * (N_BEH * DIM) + b * DIM + sl * 8];
    const float* ip = &item_emb[(size_t)i * (N_BEH * DIM) + b * DIM + sl * 8];

    float uv[16], iv[16];
    ldg_v8(up,      uv);
    ldg_v8(ip,      iv);
    ldg_v8(up + 32, uv + 8);
    ldg_v8(ip + 32, iv + 8);

    const float4* a4lo = (const float4*)&s_aw[sl * 8];
    const float4* a4hi = (const float4*)&s_aw[32 + sl * 8];
    float av[16];
    *(float4*)&av[0]  = a4lo[0];
    *(float4*)&av[4]  = a4lo[1];
    *(float4*)&av[8]  = a4hi[0];
    *(float4*)&av[12] = a4hi[1];

    float z = 0.f, a2 = 0.f;
    #pragma unroll
    for (int k = 0; k < 16; k++) {
        float d = fabsf(uv[k] - iv[k]);
        z  += d * av[k];
        a2 += d * d;
    }

    #pragma unroll
    for (int o = 2; o; o >>= 1) {
        z  += __shfl_xor_sync(FULL, z,  o);
        a2 += __shfl_xor_sync(FULL, a2, o);
    }

    z += s_ab;
    float act = (z > 0.0f) ? z : (__expf(z) - 1.0f);   // elu(alpha=1)
    float ev  = __expf(act);                            // bounded; no max shift
    if (sl == 0) {
        tpw[(size_t)b * NE + el] = ev;
        aux[(size_t)b * NE + el] = a2;
        float* dst = &g_S[b * N_USER + u];
        asm volatile("red.global.add.f32 [%0], %1;" :: "l"(dst), "f"(ev) : "memory");
    }
}

// ---------------------------------------------------------------------------
// Invert S in place.
// ---------------------------------------------------------------------------
__global__ void rcp_S_kernel() {
    int i = blockIdx.x * blockDim.x + threadIdx.x;
    if (i < N_BEH * N_USER) g_S[i] = __frcp_rn(g_S[i]);
}

// ---------------------------------------------------------------------------
// Normalize tpw (multiply by 1/S) + compact masked edges.
// v3: 8 edges per thread (two int4/float4 groups) -> double MLP, half the
// scan/atomic overhead. Tail-guarded; shuffles unconditional.
// ---------------------------------------------------------------------------
__global__ void norm_compact_kernel(const int* __restrict__ edge_index,
                                    float* __restrict__ tpw) {
    const unsigned FULL = 0xffffffffu;
    int t8 = blockIdx.x * blockDim.x + threadIdx.x;
    int idx = t8 * 8;
    bool valid = (idx < NE_ALL);

    int b = 0, e = 0;
    int4 uuA = make_int4(0,0,0,0), iiA = make_int4(0,0,0,0);
    int4 uuB = make_int4(0,0,0,0), iiB = make_int4(0,0,0,0);
    float4 wA = make_float4(0,0,0,0), wB = make_float4(0,0,0,0);
    int mA0=0,mA1=0,mA2=0,mA3=0, mB0=0,mB1=0,mB2=0,mB3=0;

    if (valid) {
        b = idx / NE;                              // NE % 8 == 0
        e = idx - b * NE;
        const int* ei = edge_index + (size_t)b * 2 * NE;
        uuA = *(const int4*)&ei[e];
        uuB = *(const int4*)&ei[e + 4];
        iiA = *(const int4*)&ei[NE + e];
        iiB = *(const int4*)&ei[NE + e + 4];
        float4 tvA = *(const float4*)&tpw[idx];
        float4 tvB = *(const float4*)&tpw[idx + 4];
        const float* Sb = &g_S[b * N_USER];        // holds 1/S
        wA.x = tvA.x * Sb[uuA.x];
        wA.y = tvA.y * Sb[uuA.y];
        wA.z = tvA.z * Sb[uuA.z];
        wA.w = tvA.w * Sb[uuA.w];
        wB.x = tvB.x * Sb[uuB.x];
        wB.y = tvB.y * Sb[uuB.y];
        wB.z = tvB.z * Sb[uuB.z];
        wB.w = tvB.w * Sb[uuB.w];
        *(float4*)&tpw[idx]     = wA;
        *(float4*)&tpw[idx + 4] = wB;
        mA0 = g_mask[iiA.x]; mA1 = g_mask[iiA.y]; mA2 = g_mask[iiA.z]; mA3 = g_mask[iiA.w];
        mB0 = g_mask[iiB.x]; mB1 = g_mask[iiB.y]; mB2 = g_mask[iiB.z]; mB3 = g_mask[iiB.w];
    }
    int cnt = mA0+mA1+mA2+mA3 + mB0+mB1+mB2+mB3;

    int lane = threadIdx.x & 31;
    int pre = cnt;
    #pragma unroll
    for (int o = 1; o < 32; o <<= 1) {
        int v = __shfl_up_sync(FULL, pre, o);
        if (lane >= o) pre += v;
    }
    int total = __shfl_sync(FULL, pre, 31);
    int excl  = pre - cnt;
    int base = 0;
    if (lane == 31 && total) base = atomicAdd(&g_cnt, total);
    base = __shfl_sync(FULL, base, 31);

    if (valid && cnt) {
        int off = base + excl;
        int us[8] = {uuA.x, uuA.y, uuA.z, uuA.w, uuB.x, uuB.y, uuB.z, uuB.w};
        int is[8] = {iiA.x, iiA.y, iiA.z, iiA.w, iiB.x, iiB.y, iiB.z, iiB.w};
        float ws[8] = {wA.x, wA.y, wA.z, wA.w, wB.x, wB.y, wB.z, wB.w};
        int ms[8] = {mA0, mA1, mA2, mA3, mB0, mB1, mB2, mB3};
        #pragma unroll
        for (int j = 0; j < 8; j++) {
            if (ms[j]) {
                g_cu[off]  = us[j] * (N_BEH * DIM) + b * DIM;
                g_cib[off] = (b * N_ITEM + is[j]) * DIM;
                g_cw[off]  = ws[j];
                off++;
            }
        }
    }
}

// ---------------------------------------------------------------------------
// Dense scatter over compacted list.
// ---------------------------------------------------------------------------
__global__ void scatter2_kernel(const float* __restrict__ user_emb) {
    int l    = threadIdx.x & 15;
    int slot = (blockIdx.x * blockDim.x + threadIdx.x) >> 4;
    int stride = (gridDim.x * blockDim.x) >> 4;
    int total = g_cnt;
    for (int e = slot; e < total; e += stride) {
        int uoff = g_cu[e];
        int aoff = g_cib[e];
        float w  = g_cw[e];
        float4 uv = *(const float4*)&user_emb[(size_t)uoff + 4 * l];
        float* dst = &g_A[(size_t)aoff + 4 * l];
        asm volatile("red.global.add.v4.f32 [%0], {%1,%2,%3,%4};"
                     :: "l"(dst), "f"(w * uv.x), "f"(w * uv.y),
                        "f"(w * uv.z), "f"(w * uv.w) : "memory");
    }
}

// ---------------------------------------------------------------------------
// Pass C: 8 rows/block, 128 threads, 4 rows/thread in matmul phases.
// ---------------------------------------------------------------------------
#define ROWS_PB 8
#define ROW_F   816
// layout per row: xs@0, qs@192(=ao), ks@384(=hh), vs@576, sc@768, mus@804, rss@808

__global__ __launch_bounds__(128)
void attn_kernel(const float* __restrict__ user_emb,
                 const float* __restrict__ item_emb,
                 const float* __restrict__ wq, const float* __restrict__ bq,
                 const float* __restrict__ wk, const float* __restrict__ bk,
                 const float* __restrict__ wv, const float* __restrict__ bv,
                 const float* __restrict__ wo, const float* __restrict__ bo,
                 const float* __restrict__ lng, const float* __restrict__ lnb,
                 const int* __restrict__ users,
                 const int* __restrict__ pos_items,
                 const int* __restrict__ neg_items,
                 float* __restrict__ emb_out) {
    __shared__ float sm[ROWS_PB * ROW_F];
    int t = threadIdx.x & 63;
    int g = threadIdx.x >> 6;
    int row0 = blockIdx.x * ROWS_PB;

    #pragma unroll
    for (int r = 0; r < 4; r++) {
        int lr  = g * 4 + r;
        int row = row0 + lr;
        int node; bool is_user;
        if (row < BATCH)          { node = users[row];                 is_user = true;  }
        else if (row < 2 * BATCH) { node = pos_items[row - BATCH];     is_user = false; }
        else                      { node = neg_items[row - 2 * BATCH]; is_user = false; }
        float* xs = sm + lr * ROW_F;
        #pragma unroll
        for (int beh = 0; beh < 3; beh++) {
            float v;
            if (is_user) {
                v = user_emb[(size_t)node * (N_BEH * DIM) + beh * DIM + t];
            } else {
                v = 2.0f * g_A[((size_t)beh * N_ITEM + node) * DIM + t]
                    + item_emb[(size_t)node * (N_BEH * DIM) + beh * DIM + t];
            }
            xs[beh * 64 + t] = v;
        }
    }
    __syncthreads();

    {
        float aq[4][3], ak[4][3], av[4][3];
        float bqv = bq[t], bkv = bk[t], bvv = bv[t];
        #pragma unroll
        for (int r = 0; r < 4; r++)
            #pragma unroll
            for (int beh = 0; beh < 3; beh++) {
                aq[r][beh] = bqv; ak[r][beh] = bkv; av[r][beh] = bvv;
            }
        #pragma unroll 4
        for (int d4 = 0; d4 < 64; d4 += 4) {
            float w1[4], w2[4], w3[4];
            #pragma unroll
            for (int k = 0; k < 4; k++) {
                w1[k] = wq[(d4 + k) * 64 + t];
                w2[k] = wk[(d4 + k) * 64 + t];
                w3[k] = wv[(d4 + k) * 64 + t];
            }
            #pragma unroll
            for (int r = 0; r < 4; r++) {
                const float* xr = sm + (g * 4 + r) * ROW_F;
                #pragma unroll
                for (int beh = 0; beh < 3; beh++) {
                    float4 x = *(const float4*)&xr[beh * 64 + d4];
                    aq[r][beh] += x.x * w1[0] + x.y * w1[1] + x.z * w1[2] + x.w * w1[3];
                    ak[r][beh] += x.x * w2[0] + x.y * w2[1] + x.z * w2[2] + x.w * w2[3];
                    av[r][beh] += x.x * w3[0] + x.y * w3[1] + x.z * w3[2] + x.w * w3[3];
                }
            }
        }
        #pragma unroll
        for (int r = 0; r < 4; r++) {
            float* base = sm + (g * 4 + r) * ROW_F;
            #pragma unroll
            for (int beh = 0; beh < 3; beh++) {
                base[192 + beh * 64 + t] = aq[r][beh];
                base[384 + beh * 64 + t] = ak[r][beh];
                base[576 + beh * 64 + t] = av[r][beh];
            }
        }
    }
    __syncthreads();

    for (int uu = threadIdx.x; uu < ROWS_PB * 36; uu += 128) {
        int lr  = uu / 36;
        int rem = uu - lr * 36;
        int h   = rem / 9;
        int qb  = (rem % 9) / 3;
        int kb  = rem % 3;
        float* base = sm + lr * ROW_F;
        float s = 0.0f;
        #pragma unroll
        for (int j = 0; j < 16; j++)
            s += base[192 + qb * 64 + h * 16 + j] * base[384 + kb * 64 + h * 16 + j];
        base[768 + rem] = s * 0.25f;
    }
    __syncthreads();

    if (threadIdx.x < ROWS_PB * 12) {
        int lr = threadIdx.x / 12;
        int p  = threadIdx.x - lr * 12;
        float* sc = sm + lr * ROW_F + 768 + p * 3;
        float s0 = sc[0], s1 = sc[1], s2 = sc[2];
        float m = fmaxf(s0, fmaxf(s1, s2));
        float e0 = expf(s0 - m), e1 = expf(s1 - m), e2 = expf(s2 - m);
        float inv = 1.0f / (e0 + e1 + e2);
        sc[0] = e0 * inv; sc[1] = e1 * inv; sc[2] = e2 * inv;
    }
    __syncthreads();

    for (int uu = threadIdx.x; uu < ROWS_PB * 64; uu += 128) {
        int lr = uu >> 6;
        int tt = uu & 63;
        int h  = tt >> 4;
        float* base = sm + lr * ROW_F;
        #pragma unroll
        for (int qb = 0; qb < 3; qb++) {
            float a = 0.0f;
            #pragma unroll
            for (int kb = 0; kb < 3; kb++)
                a += base[768 + h * 9 + qb * 3 + kb] * base[576 + kb * 64 + tt];
            base[192 + qb * 64 + tt] = a;
        }
    }
    __syncthreads();

    {
        float acc[4][3];
        float bov = bo[t];
        #pragma unroll
        for (int r = 0; r < 4; r++)
            #pragma unroll
            for (int beh = 0; beh < 3; beh++) acc[r][beh] = bov;
        #pragma unroll 4
        for (int d4 = 0; d4 < 64; d4 += 4) {
            float w[4];
            #pragma unroll
            for (int k = 0; k < 4; k++) w[k] = wo[(d4 + k) * 64 + t];
            #pragma unroll
            for (int r = 0; r < 4; r++) {
                const float* base = sm + (g * 4 + r) * ROW_F;
                #pragma unroll
                for (int beh = 0; beh < 3; beh++) {
                    float4 a = *(const float4*)&base[192 + beh * 64 + d4];
                    acc[r][beh] += a.x * w[0] + a.y * w[1] + a.z * w[2] + a.w * w[3];
                }
            }
        }
        __syncthreads();
        #pragma unroll
        for (int r = 0; r < 4; r++) {
            float* base = sm + (g * 4 + r) * ROW_F;
            #pragma unroll
            for (int beh = 0; beh < 3; beh++)
                base[384 + beh * 64 + t] = acc[r][beh] + base[beh * 64 + t];
        }
    }
    __syncthreads();

    if (threadIdx.x < ROWS_PB * 3) {
        int lr  = threadIdx.x / 3;
        int beh = threadIdx.x - lr * 3;
        float* hh = sm + lr * ROW_F + 384 + beh * 64;
        float s = 0.0f;
        #pragma unroll 8
        for (int j = 0; j < 64; j++) s += hh[j];
        float mu = s * (1.0f / 64.0f);
        float v = 0.0f;
        #pragma unroll 8
        for (int j = 0; j < 64; j++) {
            float dd = hh[j] - mu;
            v += dd * dd;
        }
        v *= (1.0f / 64.0f);
        sm[lr * ROW_F + 804 + beh] = mu;
        sm[lr * ROW_F + 808 + beh] = rsqrtf(v + LN_EPS);
    }
    __syncthreads();

    for (int uu = threadIdx.x; uu < ROWS_PB * 64; uu += 128) {
        int lr = uu >> 6;
        int tt = uu & 63;
        float* base = sm + lr * ROW_F;
        float gg = lng[tt], bb = lnb[tt];
        float gsum = 0.0f;
        #pragma unroll
        for (int beh = 0; beh < 3; beh++)
            gsum += (base[384 + beh * 64 + tt] - base[804 + beh]) * base[808 + beh] * gg + bb;
        emb_out[(size_t)(row0 + lr) * 64 + tt] = gsum;
    }
}

// ---------------------------------------------------------------------------
extern "C" void kernel_launch(void* const* d_in, const int* in_sizes, int n_in,
                              void* d_out, int out_size) {
    const float* user_emb = (const float*)d_in[0];
    const float* item_emb = (const float*)d_in[1];
    const float* alpha_w  = (const float*)d_in[2];
    const float* alpha_b  = (const float*)d_in[3];
    const float* wq = (const float*)d_in[4];
    const float* bq = (const float*)d_in[5];
    const float* wk = (const float*)d_in[6];
    const float* bk = (const float*)d_in[7];
    const float* wv = (const float*)d_in[8];
    const float* bv = (const float*)d_in[9];
    const float* wo = (const float*)d_in[10];
    const float* bo = (const float*)d_in[11];
    const float* lng = (const float*)d_in[12];
    const float* lnb = (const float*)d_in[13];
    const int* edge_index = (const int*)d_in[14];
    const int* users      = (const int*)d_in[15];
    const int* pos_items  = (const int*)d_in[16];
    const int* neg_items  = (const int*)d_in[17];

    float* out     = (float*)d_out;
    float* emb_out = out;
    float* tpw     = out + (size_t)3 * BATCH * DIM;
    float* aux     = tpw + (size_t)N_BEH * NE;

    init_kernel<<<256, 256>>>(pos_items, neg_items);
    mask_zero_kernel<<<(2 * BATCH * 48 + 255) / 256, 256>>>(pos_items, neg_items);

    edge_act_kernel<<<(size_t)NE_ALL * 4 / 256, 256>>>(user_emb, item_emb,
                                                       alpha_w, alpha_b,
                                                       edge_index, tpw, aux);

    rcp_S_kernel<<<(N_BEH * N_USER + 255) / 256, 256>>>();

    norm_compact_kernel<<<(NE_ALL / 8 + 255) / 256, 256>>>(edge_index, tpw);

    scatter2_kernel<<<4096, 256>>>(user_emb);

    attn_kernel<<<(3 * BATCH) / ROWS_PB, 128>>>(user_emb, item_emb,
                                                wq, bq, wk, bk, wv, bv, wo, bo,
                                                lng, lnb, users, pos_items, neg_items,
                                                emb_out);
}

// round 14
// speedup vs baseline: 1.2855x; 1.0005x over previous
#include <cuda_runtime.h>
#include <math.h>

#define N_USER  100000
#define N_ITEM  50000
#define DIM     64
#define N_BEH   3
#define NE      1000000
#define NE_ALL  (N_BEH * NE)
#define BATCH   4096
#define LN_EPS  1e-5f

// Scratch
__device__ float g_S[N_BEH * N_USER];
__device__ float g_A[(size_t)N_BEH * N_ITEM * DIM];
__device__ int   g_mask[N_ITEM];
__device__ int   g_cnt;
__device__ int4  g_cpack[NE_ALL];   // {uoff, aoff, w(bits), unused}

// ---------------------------------------------------------------------------
__global__ void init_kernel() {
    int idx = blockIdx.x * blockDim.x + threadIdx.x;
    int nthreads = gridDim.x * blockDim.x;
    if (idx == 0) g_cnt = 0;
    for (int i = idx; i < N_BEH * N_USER; i += nthreads)
        g_S[i] = 0.0f;
    for (int i = idx; i < N_ITEM; i += nthreads)
        g_mask[i] = 0;
}

__global__ void mask_zero_kernel(const int* __restrict__ pos_items,
                                 const int* __restrict__ neg_items) {
    int idx = blockIdx.x * blockDim.x + threadIdx.x;
    int entry = idx / 48;
    int j     = idx - entry * 48;
    if (entry >= 2 * BATCH) return;
    int item = (entry < BATCH) ? pos_items[entry] : neg_items[entry - BATCH];
    if (j == 0) g_mask[item] = 1;
    int beh = j >> 4;
    int q   = j & 15;
    float4* dst = (float4*)&g_A[((size_t)beh * N_ITEM + item) * DIM] + q;
    *dst = make_float4(0.f, 0.f, 0.f, 0.f);
}

// ---------------------------------------------------------------------------
// 256-bit load helper (sm_100a): 8 consecutive floats, 32B-aligned.
// ---------------------------------------------------------------------------
__device__ __forceinline__ void ldg_v8(const float* p, float* r) {
    asm volatile("ld.global.v8.f32 {%0,%1,%2,%3,%4,%5,%6,%7}, [%8];"
                 : "=f"(r[0]), "=f"(r[1]), "=f"(r[2]), "=f"(r[3]),
                   "=f"(r[4]), "=f"(r[5]), "=f"(r[6]), "=f"(r[7])
                 : "l"(p));
}

// ---------------------------------------------------------------------------
// Pass A (v7 proven): 4 lanes/edge, 8 edges/warp, line-aligned v8 loads,
// smem alpha, fast __expf, __launch_bounds__(256,7).
// ---------------------------------------------------------------------------
__global__ __launch_bounds__(256, 7)
void edge_act_kernel(const float* __restrict__ user_emb,
                     const float* __restrict__ item_emb,
                     const float* __restrict__ alpha_w,
                     const float* __restrict__ alpha_b,
                     const int*   __restrict__ edge_index,
                     float* __restrict__ tpw,
                     float* __restrict__ aux) {
    __shared__ float s_aw[64];
    __shared__ float s_ab;

    const unsigned FULL = 0xffffffffu;
    int tid  = threadIdx.x;
    int lane = tid & 31;
    int sl   = lane & 3;
    size_t e = ((size_t)blockIdx.x * blockDim.x + tid) >> 2;
    int b    = (int)(e / NE);            // uniform per block
    int el   = (int)(e - (size_t)b * NE);

    if (tid < 64) s_aw[tid] = alpha_w[b * 64 + tid];
    if (tid == 64) s_ab = alpha_b[b];
    __syncthreads();

    const int* ei = edge_index + (size_t)b * 2 * NE;
    int u = ei[el];
    int i = ei[NE + el];

    const float* up = &user_emb[(size_t)u * (N_BEH * DIM) + b * DIM + sl * 8];
    const float* ip = &item_emb[(size_t)i * (N_BEH * DIM) + b * DIM + sl * 8];

    float uv[16], iv[16];
    ldg_v8(up,      uv);
    ldg_v8(ip,      iv);
    ldg_v8(up + 32, uv + 8);
    ldg_v8(ip + 32, iv + 8);

    const float4* a4lo = (const float4*)&s_aw[sl * 8];
    const float4* a4hi = (const float4*)&s_aw[32 + sl * 8];
    float av[16];
    *(float4*)&av[0]  = a4lo[0];
    *(float4*)&av[4]  = a4lo[1];
    *(float4*)&av[8]  = a4hi[0];
    *(float4*)&av[12] = a4hi[1];

    float z = 0.f, a2 = 0.f;
    #pragma unroll
    for (int k = 0; k < 16; k++) {
        float d = fabsf(uv[k] - iv[k]);
        z  += d * av[k];
        a2 += d * d;
    }

    #pragma unroll
    for (int o = 2; o; o >>= 1) {
        z  += __shfl_xor_sync(FULL, z,  o);
        a2 += __shfl_xor_sync(FULL, a2, o);
    }

    z += s_ab;
    float act = (z > 0.0f) ? z : (__expf(z) - 1.0f);   // elu(alpha=1)
    float ev  = __expf(act);                            // bounded; no max shift
    if (sl == 0) {
        tpw[(size_t)b * NE + el] = ev;
        aux[(size_t)b * NE + el] = a2;
        float* dst = &g_S[b * N_USER + u];
        asm volatile("red.global.add.f32 [%0], %1;" :: "l"(dst), "f"(ev) : "memory");
    }
}

// ---------------------------------------------------------------------------
// Normalize tpw (inline __frcp_rn of S) + compact masked edges into packed
// 16B records. 8 edges/thread; tail-guarded; shuffles unconditional.
// ---------------------------------------------------------------------------
__global__ void norm_compact_kernel(const int* __restrict__ edge_index,
                                    float* __restrict__ tpw) {
    const unsigned FULL = 0xffffffffu;
    int t8 = blockIdx.x * blockDim.x + threadIdx.x;
    int idx = t8 * 8;
    bool valid = (idx < NE_ALL);

    int b = 0, e = 0;
    int4 uuA = make_int4(0,0,0,0), iiA = make_int4(0,0,0,0);
    int4 uuB = make_int4(0,0,0,0), iiB = make_int4(0,0,0,0);
    float4 wA = make_float4(0,0,0,0), wB = make_float4(0,0,0,0);
    int mA0=0,mA1=0,mA2=0,mA3=0, mB0=0,mB1=0,mB2=0,mB3=0;

    if (valid) {
        b = idx / NE;                              // NE % 8 == 0
        e = idx - b * NE;
        const int* ei = edge_index + (size_t)b * 2 * NE;
        uuA = *(const int4*)&ei[e];
        uuB = *(const int4*)&ei[e + 4];
        iiA = *(const int4*)&ei[NE + e];
        iiB = *(const int4*)&ei[NE + e + 4];
        float4 tvA = *(const float4*)&tpw[idx];
        float4 tvB = *(const float4*)&tpw[idx + 4];
        const float* Sb = &g_S[b * N_USER];        // holds S; invert inline
        wA.x = tvA.x * __frcp_rn(Sb[uuA.x]);
        wA.y = tvA.y * __frcp_rn(Sb[uuA.y]);
        wA.z = tvA.z * __frcp_rn(Sb[uuA.z]);
        wA.w = tvA.w * __frcp_rn(Sb[uuA.w]);
        wB.x = tvB.x * __frcp_rn(Sb[uuB.x]);
        wB.y = tvB.y * __frcp_rn(Sb[uuB.y]);
        wB.z = tvB.z * __frcp_rn(Sb[uuB.z]);
        wB.w = tvB.w * __frcp_rn(Sb[uuB.w]);
        *(float4*)&tpw[idx]     = wA;
        *(float4*)&tpw[idx + 4] = wB;
        mA0 = g_mask[iiA.x]; mA1 = g_mask[iiA.y]; mA2 = g_mask[iiA.z]; mA3 = g_mask[iiA.w];
        mB0 = g_mask[iiB.x]; mB1 = g_mask[iiB.y]; mB2 = g_mask[iiB.z]; mB3 = g_mask[iiB.w];
    }
    int cnt = mA0+mA1+mA2+mA3 + mB0+mB1+mB2+mB3;

    int lane = threadIdx.x & 31;
    int pre = cnt;
    #pragma unroll
    for (int o = 1; o < 32; o <<= 1) {
        int v = __shfl_up_sync(FULL, pre, o);
        if (lane >= o) pre += v;
    }
    int total = __shfl_sync(FULL, pre, 31);
    int excl  = pre - cnt;
    int base = 0;
    if (lane == 31 && total) base = atomicAdd(&g_cnt, total);
    base = __shfl_sync(FULL, base, 31);

    if (valid && cnt) {
        int off = base + excl;
        int us[8] = {uuA.x, uuA.y, uuA.z, uuA.w, uuB.x, uuB.y, uuB.z, uuB.w};
        int is[8] = {iiA.x, iiA.y, iiA.z, iiA.w, iiB.x, iiB.y, iiB.z, iiB.w};
        float ws[8] = {wA.x, wA.y, wA.z, wA.w, wB.x, wB.y, wB.z, wB.w};
        int ms[8] = {mA0, mA1, mA2, mA3, mB0, mB1, mB2, mB3};
        #pragma unroll
        for (int j = 0; j < 8; j++) {
            if (ms[j]) {
                g_cpack[off] = make_int4(us[j] * (N_BEH * DIM) + b * DIM,
                                         (b * N_ITEM + is[j]) * DIM,
                                         __float_as_int(ws[j]), 0);
                off++;
            }
        }
    }
}

// ---------------------------------------------------------------------------
// Dense scatter over compacted packed records (one LDG.128 per edge group).
// ---------------------------------------------------------------------------
__global__ void scatter2_kernel(const float* __restrict__ user_emb) {
    int l    = threadIdx.x & 15;
    int slot = (blockIdx.x * blockDim.x + threadIdx.x) >> 4;
    int stride = (gridDim.x * blockDim.x) >> 4;
    int total = g_cnt;
    for (int e = slot; e < total; e += stride) {
        int4 p = g_cpack[e];
        float w = __int_as_float(p.z);
        float4 uv = *(const float4*)&user_emb[(size_t)p.x + 4 * l];
        float* dst = &g_A[(size_t)p.y + 4 * l];
        asm volatile("red.global.add.v4.f32 [%0], {%1,%2,%3,%4};"
                     :: "l"(dst), "f"(w * uv.x), "f"(w * uv.y),
                        "f"(w * uv.z), "f"(w * uv.w) : "memory");
    }
}

// ---------------------------------------------------------------------------
// Pass C: 8 rows/block, 128 threads, 4 rows/thread in matmul phases.
// ---------------------------------------------------------------------------
#define ROWS_PB 8
#define ROW_F   816
// layout per row: xs@0, qs@192(=ao), ks@384(=hh), vs@576, sc@768, mus@804, rss@808

__global__ __launch_bounds__(128)
void attn_kernel(const float* __restrict__ user_emb,
                 const float* __restrict__ item_emb,
                 const float* __restrict__ wq, const float* __restrict__ bq,
                 const float* __restrict__ wk, const float* __restrict__ bk,
                 const float* __restrict__ wv, const float* __restrict__ bv,
                 const float* __restrict__ wo, const float* __restrict__ bo,
                 const float* __restrict__ lng, const float* __restrict__ lnb,
                 const int* __restrict__ users,
                 const int* __restrict__ pos_items,
                 const int* __restrict__ neg_items,
                 float* __restrict__ emb_out) {
    __shared__ float sm[ROWS_PB * ROW_F];
    int t = threadIdx.x & 63;
    int g = threadIdx.x >> 6;
    int row0 = blockIdx.x * ROWS_PB;

    #pragma unroll
    for (int r = 0; r < 4; r++) {
        int lr  = g * 4 + r;
        int row = row0 + lr;
        int node; bool is_user;
        if (row < BATCH)          { node = users[row];                 is_user = true;  }
        else if (row < 2 * BATCH) { node = pos_items[row - BATCH];     is_user = false; }
        else                      { node = neg_items[row - 2 * BATCH]; is_user = false; }
        float* xs = sm + lr * ROW_F;
        #pragma unroll
        for (int beh = 0; beh < 3; beh++) {
            float v;
            if (is_user) {
                v = user_emb[(size_t)node * (N_BEH * DIM) + beh * DIM + t];
            } else {
                v = 2.0f * g_A[((size_t)beh * N_ITEM + node) * DIM + t]
                    + item_emb[(size_t)node * (N_BEH * DIM) + beh * DIM + t];
            }
            xs[beh * 64 + t] = v;
        }
    }
    __syncthreads();

    {
        float aq[4][3], ak[4][3], av[4][3];
        float bqv = bq[t], bkv = bk[t], bvv = bv[t];
        #pragma unroll
        for (int r = 0; r < 4; r++)
            #pragma unroll
            for (int beh = 0; beh < 3; beh++) {
                aq[r][beh] = bqv; ak[r][beh] = bkv; av[r][beh] = bvv;
            }
        #pragma unroll 4
        for (int d4 = 0; d4 < 64; d4 += 4) {
            float w1[4], w2[4], w3[4];
            #pragma unroll
            for (int k = 0; k < 4; k++) {
                w1[k] = wq[(d4 + k) * 64 + t];
                w2[k] = wk[(d4 + k) * 64 + t];
                w3[k] = wv[(d4 + k) * 64 + t];
            }
            #pragma unroll
            for (int r = 0; r < 4; r++) {
                const float* xr = sm + (g * 4 + r) * ROW_F;
                #pragma unroll
                for (int beh = 0; beh < 3; beh++) {
                    float4 x = *(const float4*)&xr[beh * 64 + d4];
                    aq[r][beh] += x.x * w1[0] + x.y * w1[1] + x.z * w1[2] + x.w * w1[3];
                    ak[r][beh] += x.x * w2[0] + x.y * w2[1] + x.z * w2[2] + x.w * w2[3];
                    av[r][beh] += x.x * w3[0] + x.y * w3[1] + x.z * w3[2] + x.w * w3[3];
                }
            }
        }
        #pragma unroll
        for (int r = 0; r < 4; r++) {
            float* base = sm + (g * 4 + r) * ROW_F;
            #pragma unroll
            for (int beh = 0; beh < 3; beh++) {
                base[192 + beh * 64 + t] = aq[r][beh];
                base[384 + beh * 64 + t] = ak[r][beh];
                base[576 + beh * 64 + t] = av[r][beh];
            }
        }
    }
    __syncthreads();

    for (int uu = threadIdx.x; uu < ROWS_PB * 36; uu += 128) {
        int lr  = uu / 36;
        int rem = uu - lr * 36;
        int h   = rem / 9;
        int qb  = (rem % 9) / 3;
        int kb  = rem % 3;
        float* base = sm + lr * ROW_F;
        float s = 0.0f;
        #pragma unroll
        for (int j = 0; j < 16; j++)
            s += base[192 + qb * 64 + h * 16 + j] * base[384 + kb * 64 + h * 16 + j];
        base[768 + rem] = s * 0.25f;
    }
    __syncthreads();

    if (threadIdx.x < ROWS_PB * 12) {
        int lr = threadIdx.x / 12;
        int p  = threadIdx.x - lr * 12;
        float* sc = sm + lr * ROW_F + 768 + p * 3;
        float s0 = sc[0], s1 = sc[1], s2 = sc[2];
        float m = fmaxf(s0, fmaxf(s1, s2));
        float e0 = expf(s0 - m), e1 = expf(s1 - m), e2 = expf(s2 - m);
        float inv = 1.0f / (e0 + e1 + e2);
        sc[0] = e0 * inv; sc[1] = e1 * inv; sc[2] = e2 * inv;
    }
    __syncthreads();

    for (int uu = threadIdx.x; uu < ROWS_PB * 64; uu += 128) {
        int lr = uu >> 6;
        int tt = uu & 63;
        int h  = tt >> 4;
        float* base = sm + lr * ROW_F;
        #pragma unroll
        for (int qb = 0; qb < 3; qb++) {
            float a = 0.0f;
            #pragma unroll
            for (int kb = 0; kb < 3; kb++)
                a += base[768 + h * 9 + qb * 3 + kb] * base[576 + kb * 64 + tt];
            base[192 + qb * 64 + tt] = a;
        }
    }
    __syncthreads();

    {
        float acc[4][3];
        float bov = bo[t];
        #pragma unroll
        for (int r = 0; r < 4; r++)
            #pragma unroll
            for (int beh = 0; beh < 3; beh++) acc[r][beh] = bov;
        #pragma unroll 4
        for (int d4 = 0; d4 < 64; d4 += 4) {
            float w[4];
            #pragma unroll
            for (int k = 0; k < 4; k++) w[k] = wo[(d4 + k) * 64 + t];
            #pragma unroll
            for (int r = 0; r < 4; r++) {
                const float* base = sm + (g * 4 + r) * ROW_F;
                #pragma unroll
                for (int beh = 0; beh < 3; beh++) {
                    float4 a = *(const float4*)&base[192 + beh * 64 + d4];
                    acc[r][beh] += a.x * w[0] + a.y * w[1] + a.z * w[2] + a.w * w[3];
                }
            }
        }
        __syncthreads();
        #pragma unroll
        for (int r = 0; r < 4; r++) {
            float* base = sm + (g * 4 + r) * ROW_F;
            #pragma unroll
            for (int beh = 0; beh < 3; beh++)
                base[384 + beh * 64 + t] = acc[r][beh] + base[beh * 64 + t];
        }
    }
    __syncthreads();

    if (threadIdx.x < ROWS_PB * 3) {
        int lr  = threadIdx.x / 3;
        int beh = threadIdx.x - lr * 3;
        float* hh = sm + lr * ROW_F + 384 + beh * 64;
        float s = 0.0f;
        #pragma unroll 8
        for (int j = 0; j < 64; j++) s += hh[j];
        float mu = s * (1.0f / 64.0f);
        float v = 0.0f;
        #pragma unroll 8
        for (int j = 0; j < 64; j++) {
            float dd = hh[j] - mu;
            v += dd * dd;
        }
        v *= (1.0f / 64.0f);
        sm[lr * ROW_F + 804 + beh] = mu;
        sm[lr * ROW_F + 808 + beh] = rsqrtf(v + LN_EPS);
    }
    __syncthreads();

    for (int uu = threadIdx.x; uu < ROWS_PB * 64; uu += 128) {
        int lr = uu >> 6;
        int tt = uu & 63;
        float* base = sm + lr * ROW_F;
        float gg = lng[tt], bb = lnb[tt];
        float gsum = 0.0f;
        #pragma unroll
        for (int beh = 0; beh < 3; beh++)
            gsum += (base[384 + beh * 64 + tt] - base[804 + beh]) * base[808 + beh] * gg + bb;
        emb_out[(size_t)(row0 + lr) * 64 + tt] = gsum;
    }
}

// ---------------------------------------------------------------------------
extern "C" void kernel_launch(void* const* d_in, const int* in_sizes, int n_in,
                              void* d_out, int out_size) {
    const float* user_emb = (const float*)d_in[0];
    const float* item_emb = (const float*)d_in[1];
    const float* alpha_w  = (const float*)d_in[2];
    const float* alpha_b  = (const float*)d_in[3];
    const float* wq = (const float*)d_in[4];
    const float* bq = (const float*)d_in[5];
    const float* wk = (const float*)d_in[6];
    const float* bk = (const float*)d_in[7];
    const float* wv = (const float*)d_in[8];
    const float* bv = (const float*)d_in[9];
    const float* wo = (const float*)d_in[10];
    const float* bo = (const float*)d_in[11];
    const float* lng = (const float*)d_in[12];
    const float* lnb = (const float*)d_in[13];
    const int* edge_index = (const int*)d_in[14];
    const int* users      = (const int*)d_in[15];
    const int* pos_items  = (const int*)d_in[16];
    const int* neg_items  = (const int*)d_in[17];

    float* out     = (float*)d_out;
    float* emb_out = out;
    float* tpw     = out + (size_t)3 * BATCH * DIM;
    float* aux     = tpw + (size_t)N_BEH * NE;

    init_kernel<<<256, 256>>>();
    mask_zero_kernel<<<(2 * BATCH * 48 + 255) / 256, 256>>>(pos_items, neg_items);

    edge_act_kernel<<<(size_t)NE_ALL * 4 / 256, 256>>>(user_emb, item_emb,
                                                       alpha_w, alpha_b,
                                                       edge_index, tpw, aux);

    norm_compact_kernel<<<(NE_ALL / 8 + 255) / 256, 256>>>(edge_index, tpw);

    scatter2_kernel<<<4096, 256>>>(user_emb);

    attn_kernel<<<(3 * BATCH) / ROWS_PB, 128>>>(user_emb, item_emb,
                                                wq, bq, wk, bk, wv, bv, wo, bo,
                                                lng, lnb, users, pos_items, neg_items,
                                                emb_out);
}

// round 16
// speedup vs baseline: 1.3126x; 1.0211x over previous
#include <cuda_runtime.h>
#include <math.h>

#define N_USER  100000
#define N_ITEM  50000
#define DIM     64
#define N_BEH   3
#define NE      1000000
#define NE_ALL  (N_BEH * NE)
#define BATCH   4096
#define LN_EPS  1e-5f

// Scratch
__device__ float g_S[N_BEH * N_USER];
__device__ float g_A[(size_t)N_BEH * N_ITEM * DIM];
__device__ int   g_mask[N_ITEM];
__device__ int   g_cnt;
__device__ int4  g_cpack[NE_ALL];   // {uoff, aoff, w(bits), unused}

// ---------------------------------------------------------------------------
__global__ void init_kernel() {
    int idx = blockIdx.x * blockDim.x + threadIdx.x;
    int nthreads = gridDim.x * blockDim.x;
    if (idx == 0) g_cnt = 0;
    for (int i = idx; i < N_BEH * N_USER; i += nthreads)
        g_S[i] = 0.0f;
    for (int i = idx; i < N_ITEM; i += nthreads)
        g_mask[i] = 0;
}

__global__ void mask_zero_kernel(const int* __restrict__ pos_items,
                                 const int* __restrict__ neg_items) {
    int idx = blockIdx.x * blockDim.x + threadIdx.x;
    int entry = idx / 48;
    int j     = idx - entry * 48;
    if (entry >= 2 * BATCH) return;
    int item = (entry < BATCH) ? pos_items[entry] : neg_items[entry - BATCH];
    if (j == 0) g_mask[item] = 1;
    int beh = j >> 4;
    int q   = j & 15;
    float4* dst = (float4*)&g_A[((size_t)beh * N_ITEM + item) * DIM] + q;
    *dst = make_float4(0.f, 0.f, 0.f, 0.f);
}

// ---------------------------------------------------------------------------
// 256-bit load helper (sm_100a): 8 consecutive floats, 32B-aligned.
// ---------------------------------------------------------------------------
__device__ __forceinline__ void ldg_v8(const float* p, float* r) {
    asm volatile("ld.global.v8.f32 {%0,%1,%2,%3,%4,%5,%6,%7}, [%8];"
                 : "=f"(r[0]), "=f"(r[1]), "=f"(r[2]), "=f"(r[3]),
                   "=f"(r[4]), "=f"(r[5]), "=f"(r[6]), "=f"(r[7])
                 : "l"(p));
}

// ---------------------------------------------------------------------------
// Pass A (v7 proven): 4 lanes/edge, 8 edges/warp, line-aligned v8 loads,
// smem alpha, fast __expf, __launch_bounds__(256,7).
// ---------------------------------------------------------------------------
__global__ __launch_bounds__(256, 7)
void edge_act_kernel(const float* __restrict__ user_emb,
                     const float* __restrict__ item_emb,
                     const float* __restrict__ alpha_w,
                     const float* __restrict__ alpha_b,
                     const int*   __restrict__ edge_index,
                     float* __restrict__ tpw,
                     float* __restrict__ aux) {
    __shared__ float s_aw[64];
    __shared__ float s_ab;

    const unsigned FULL = 0xffffffffu;
    int tid  = threadIdx.x;
    int lane = tid & 31;
    int sl   = lane & 3;
    size_t e = ((size_t)blockIdx.x * blockDim.x + tid) >> 2;
    int b    = (int)(e / NE);            // uniform per block
    int el   = (int)(e - (size_t)b * NE);

    if (tid < 64) s_aw[tid] = alpha_w[b * 64 + tid];
    if (tid == 64) s_ab = alpha_b[b];
    __syncthreads();

    const int* ei = edge_index + (size_t)b * 2 * NE;
    int u = ei[el];
    int i = ei[NE + el];

    const float* up = &user_emb[(size_t)u * (N_BEH * DIM) + b * DIM + sl * 8];
    const float* ip = &item_emb[(size_t)i * (N_BEH * DIM) + b * DIM + sl * 8];

    float uv[16], iv[16];
    ldg_v8(up,      uv);
    ldg_v8(ip,      iv);
    ldg_v8(up + 32, uv + 8);
    ldg_v8(ip + 32, iv + 8);

    const float4* a4lo = (const float4*)&s_aw[sl * 8];
    const float4* a4hi = (const float4*)&s_aw[32 + sl * 8];
    float av[16];
    *(float4*)&av[0]  = a4lo[0];
    *(float4*)&av[4]  = a4lo[1];
    *(float4*)&av[8]  = a4hi[0];
    *(float4*)&av[12] = a4hi[1];

    float z = 0.f, a2 = 0.f;
    #pragma unroll
    for (int k = 0; k < 16; k++) {
        float d = fabsf(uv[k] - iv[k]);
        z  += d * av[k];
        a2 += d * d;
    }

    #pragma unroll
    for (int o = 2; o; o >>= 1) {
        z  += __shfl_xor_sync(FULL, z,  o);
        a2 += __shfl_xor_sync(FULL, a2, o);
    }

    z += s_ab;
    float act = (z > 0.0f) ? z : (__expf(z) - 1.0f);   // elu(alpha=1)
    float ev  = __expf(act);                            // bounded; no max shift
    if (sl == 0) {
        tpw[(size_t)b * NE + el] = ev;
        aux[(size_t)b * NE + el] = a2;
        float* dst = &g_S[b * N_USER + u];
        asm volatile("red.global.add.f32 [%0], %1;" :: "l"(dst), "f"(ev) : "memory");
    }
}

// ---------------------------------------------------------------------------
// Normalize tpw + compact. v5: only indices + packed mask bits live across
// the warp scan; tpw load / rcp / store / record emission AFTER the scan,
// group A then group B. 8 edges/thread, tail-guarded.
// ---------------------------------------------------------------------------
__global__ __launch_bounds__(256, 6)
void norm_compact_kernel(const int* __restrict__ edge_index,
                         float* __restrict__ tpw) {
    const unsigned FULL = 0xffffffffu;
    int t8 = blockIdx.x * blockDim.x + threadIdx.x;
    int idx = t8 * 8;
    bool valid = (idx < NE_ALL);

    int b = 0, e = 0;
    int4 uuA = make_int4(0,0,0,0), iiA = make_int4(0,0,0,0);
    int4 uuB = make_int4(0,0,0,0), iiB = make_int4(0,0,0,0);
    int mbits = 0;

    if (valid) {
        b = idx / NE;                              // NE % 8 == 0
        e = idx - b * NE;
        const int* ei = edge_index + (size_t)b * 2 * NE;
        uuA = *(const int4*)&ei[e];
        uuB = *(const int4*)&ei[e + 4];
        iiA = *(const int4*)&ei[NE + e];
        iiB = *(const int4*)&ei[NE + e + 4];
        mbits  = (g_mask[iiA.x] != 0)       | ((g_mask[iiA.y] != 0) << 1)
               | ((g_mask[iiA.z] != 0) << 2)| ((g_mask[iiA.w] != 0) << 3)
               | ((g_mask[iiB.x] != 0) << 4)| ((g_mask[iiB.y] != 0) << 5)
               | ((g_mask[iiB.z] != 0) << 6)| ((g_mask[iiB.w] != 0) << 7);
    }
    int cnt = __popc(mbits);

    int lane = threadIdx.x & 31;
    int pre = cnt;
    #pragma unroll
    for (int o = 1; o < 32; o <<= 1) {
        int v = __shfl_up_sync(FULL, pre, o);
        if (lane >= o) pre += v;
    }
    int total = __shfl_sync(FULL, pre, 31);
    int excl  = pre - cnt;
    int base = 0;
    if (lane == 31 && total) base = atomicAdd(&g_cnt, total);
    base = __shfl_sync(FULL, base, 31);

    if (valid) {
        const float* Sb = &g_S[b * N_USER];
        int off = base + excl;
        int ubase = b * DIM;
        int ibase = b * N_ITEM;

        // group A
        {
            float4 tv = *(const float4*)&tpw[idx];
            float4 w;
            w.x = tv.x * __frcp_rn(Sb[uuA.x]);
            w.y = tv.y * __frcp_rn(Sb[uuA.y]);
            w.z = tv.z * __frcp_rn(Sb[uuA.z]);
            w.w = tv.w * __frcp_rn(Sb[uuA.w]);
            *(float4*)&tpw[idx] = w;
            if (mbits & 1)  g_cpack[off++] = make_int4(uuA.x * (N_BEH*DIM) + ubase, (ibase + iiA.x) * DIM, __float_as_int(w.x), 0);
            if (mbits & 2)  g_cpack[off++] = make_int4(uuA.y * (N_BEH*DIM) + ubase, (ibase + iiA.y) * DIM, __float_as_int(w.y), 0);
            if (mbits & 4)  g_cpack[off++] = make_int4(uuA.z * (N_BEH*DIM) + ubase, (ibase + iiA.z) * DIM, __float_as_int(w.z), 0);
            if (mbits & 8)  g_cpack[off++] = make_int4(uuA.w * (N_BEH*DIM) + ubase, (ibase + iiA.w) * DIM, __float_as_int(w.w), 0);
        }
        // group B
        {
            float4 tv = *(const float4*)&tpw[idx + 4];
            float4 w;
            w.x = tv.x * __frcp_rn(Sb[uuB.x]);
            w.y = tv.y * __frcp_rn(Sb[uuB.y]);
            w.z = tv.z * __frcp_rn(Sb[uuB.z]);
            w.w = tv.w * __frcp_rn(Sb[uuB.w]);
            *(float4*)&tpw[idx + 4] = w;
            if (mbits & 16)  g_cpack[off++] = make_int4(uuB.x * (N_BEH*DIM) + ubase, (ibase + iiB.x) * DIM, __float_as_int(w.x), 0);
            if (mbits & 32)  g_cpack[off++] = make_int4(uuB.y * (N_BEH*DIM) + ubase, (ibase + iiB.y) * DIM, __float_as_int(w.y), 0);
            if (mbits & 64)  g_cpack[off++] = make_int4(uuB.z * (N_BEH*DIM) + ubase, (ibase + iiB.z) * DIM, __float_as_int(w.z), 0);
            if (mbits & 128) g_cpack[off++] = make_int4(uuB.w * (N_BEH*DIM) + ubase, (ibase + iiB.w) * DIM, __float_as_int(w.w), 0);
        }
    }
}

// ---------------------------------------------------------------------------
// Dense scatter over compacted records, x2 unrolled for MLP.
// ---------------------------------------------------------------------------
__global__ void scatter2_kernel(const float* __restrict__ user_emb) {
    int l    = threadIdx.x & 15;
    int slot = (blockIdx.x * blockDim.x + threadIdx.x) >> 4;
    int stride = (gridDim.x * blockDim.x) >> 4;
    int total = g_cnt;
    int e = slot;
    for (; e + stride < total; e += 2 * stride) {
        int4 p0 = g_cpack[e];
        int4 p1 = g_cpack[e + stride];
        float4 uv0 = *(const float4*)&user_emb[(size_t)p0.x + 4 * l];
        float4 uv1 = *(const float4*)&user_emb[(size_t)p1.x + 4 * l];
        float w0 = __int_as_float(p0.z);
        float w1 = __int_as_float(p1.z);
        float* d0 = &g_A[(size_t)p0.y + 4 * l];
        float* d1 = &g_A[(size_t)p1.y + 4 * l];
        asm volatile("red.global.add.v4.f32 [%0], {%1,%2,%3,%4};"
                     :: "l"(d0), "f"(w0 * uv0.x), "f"(w0 * uv0.y),
                        "f"(w0 * uv0.z), "f"(w0 * uv0.w) : "memory");
        asm volatile("red.global.add.v4.f32 [%0], {%1,%2,%3,%4};"
                     :: "l"(d1), "f"(w1 * uv1.x), "f"(w1 * uv1.y),
                        "f"(w1 * uv1.z), "f"(w1 * uv1.w) : "memory");
    }
    if (e < total) {
        int4 p = g_cpack[e];
        float w = __int_as_float(p.z);
        float4 uv = *(const float4*)&user_emb[(size_t)p.x + 4 * l];
        float* dst = &g_A[(size_t)p.y + 4 * l];
        asm volatile("red.global.add.v4.f32 [%0], {%1,%2,%3,%4};"
                     :: "l"(dst), "f"(w * uv.x), "f"(w * uv.y),
                        "f"(w * uv.z), "f"(w * uv.w) : "memory");
    }
}

// ---------------------------------------------------------------------------
// Pass C: 8 rows/block, 128 threads, 4 rows/thread in matmul phases.
// ---------------------------------------------------------------------------
#define ROWS_PB 8
#define ROW_F   816
// layout per row: xs@0, qs@192(=ao), ks@384(=hh), vs@576, sc@768, mus@804, rss@808

__global__ __launch_bounds__(128)
void attn_kernel(const float* __restrict__ user_emb,
                 const float* __restrict__ item_emb,
                 const float* __restrict__ wq, const float* __restrict__ bq,
                 const float* __restrict__ wk, const float* __restrict__ bk,
                 const float* __restrict__ wv, const float* __restrict__ bv,
                 const float* __restrict__ wo, const float* __restrict__ bo,
                 const float* __restrict__ lng, const float* __restrict__ lnb,
                 const int* __restrict__ users,
                 const int* __restrict__ pos_items,
                 const int* __restrict__ neg_items,
                 float* __restrict__ emb_out) {
    __shared__ float sm[ROWS_PB * ROW_F];
    int t = threadIdx.x & 63;
    int g = threadIdx.x >> 6;
    int row0 = blockIdx.x * ROWS_PB;

    #pragma unroll
    for (int r = 0; r < 4; r++) {
        int lr  = g * 4 + r;
        int row = row0 + lr;
        int node; bool is_user;
        if (row < BATCH)          { node = users[row];                 is_user = true;  }
        else if (row < 2 * BATCH) { node = pos_items[row - BATCH];     is_user = false; }
        else                      { node = neg_items[row - 2 * BATCH]; is_user = false; }
        float* xs = sm + lr * ROW_F;
        #pragma unroll
        for (int beh = 0; beh < 3; beh++) {
            float v;
            if (is_user) {
                v = user_emb[(size_t)node * (N_BEH * DIM) + beh * DIM + t];
            } else {
                v = 2.0f * g_A[((size_t)beh * N_ITEM + node) * DIM + t]
                    + item_emb[(size_t)node * (N_BEH * DIM) + beh * DIM + t];
            }
            xs[beh * 64 + t] = v;
        }
    }
    __syncthreads();

    {
        float aq[4][3], ak[4][3], av[4][3];
        float bqv = bq[t], bkv = bk[t], bvv = bv[t];
        #pragma unroll
        for (int r = 0; r < 4; r++)
            #pragma unroll
            for (int beh = 0; beh < 3; beh++) {
                aq[r][beh] = bqv; ak[r][beh] = bkv; av[r][beh] = bvv;
            }
        #pragma unroll 4
        for (int d4 = 0; d4 < 64; d4 += 4) {
            float w1[4], w2[4], w3[4];
            #pragma unroll
            for (int k = 0; k < 4; k++) {
                w1[k] = wq[(d4 + k) * 64 + t];
                w2[k] = wk[(d4 + k) * 64 + t];
                w3[k] = wv[(d4 + k) * 64 + t];
            }
            #pragma unroll
            for (int r = 0; r < 4; r++) {
                const float* xr = sm + (g * 4 + r) * ROW_F;
                #pragma unroll
                for (int beh = 0; beh < 3; beh++) {
                    float4 x = *(const float4*)&xr[beh * 64 + d4];
                    aq[r][beh] += x.x * w1[0] + x.y * w1[1] + x.z * w1[2] + x.w * w1[3];
                    ak[r][beh] += x.x * w2[0] + x.y * w2[1] + x.z * w2[2] + x.w * w2[3];
                    av[r][beh] += x.x * w3[0] + x.y * w3[1] + x.z * w3[2] + x.w * w3[3];
                }
            }
        }
        #pragma unroll
        for (int r = 0; r < 4; r++) {
            float* base = sm + (g * 4 + r) * ROW_F;
            #pragma unroll
            for (int beh = 0; beh < 3; beh++) {
                base[192 + beh * 64 + t] = aq[r][beh];
                base[384 + beh * 64 + t] = ak[r][beh];
                base[576 + beh * 64 + t] = av[r][beh];
            }
        }
    }
    __syncthreads();

    for (int uu = threadIdx.x; uu < ROWS_PB * 36; uu += 128) {
        int lr  = uu / 36;
        int rem = uu - lr * 36;
        int h   = rem / 9;
        int qb  = (rem % 9) / 3;
        int kb  = rem % 3;
        float* base = sm + lr * ROW_F;
        float s = 0.0f;
        #pragma unroll
        for (int j = 0; j < 16; j++)
            s += base[192 + qb * 64 + h * 16 + j] * base[384 + kb * 64 + h * 16 + j];
        base[768 + rem] = s * 0.25f;
    }
    __syncthreads();

    if (threadIdx.x < ROWS_PB * 12) {
        int lr = threadIdx.x / 12;
        int p  = threadIdx.x - lr * 12;
        float* sc = sm + lr * ROW_F + 768 + p * 3;
        float s0 = sc[0], s1 = sc[1], s2 = sc[2];
        float m = fmaxf(s0, fmaxf(s1, s2));
        float e0 = expf(s0 - m), e1 = expf(s1 - m), e2 = expf(s2 - m);
        float inv = 1.0f / (e0 + e1 + e2);
        sc[0] = e0 * inv; sc[1] = e1 * inv; sc[2] = e2 * inv;
    }
    __syncthreads();

    for (int uu = threadIdx.x; uu < ROWS_PB * 64; uu += 128) {
        int lr = uu >> 6;
        int tt = uu & 63;
        int h  = tt >> 4;
        float* base = sm + lr * ROW_F;
        #pragma unroll
        for (int qb = 0; qb < 3; qb++) {
            float a = 0.0f;
            #pragma unroll
            for (int kb = 0; kb < 3; kb++)
                a += base[768 + h * 9 + qb * 3 + kb] * base[576 + kb * 64 + tt];
            base[192 + qb * 64 + tt] = a;
        }
    }
    __syncthreads();

    {
        float acc[4][3];
        float bov = bo[t];
        #pragma unroll
        for (int r = 0; r < 4; r++)
            #pragma unroll
            for (int beh = 0; beh < 3; beh++) acc[r][beh] = bov;
        #pragma unroll 4
        for (int d4 = 0; d4 < 64; d4 += 4) {
            float w[4];
            #pragma unroll
            for (int k = 0; k < 4; k++) w[k] = wo[(d4 + k) * 64 + t];
            #pragma unroll
            for (int r = 0; r < 4; r++) {
                const float* base = sm + (g * 4 + r) * ROW_F;
                #pragma unroll
                for (int beh = 0; beh < 3; beh++) {
                    float4 a = *(const float4*)&base[192 + beh * 64 + d4];
                    acc[r][beh] += a.x * w[0] + a.y * w[1] + a.z * w[2] + a.w * w[3];
                }
            }
        }
        __syncthreads();
        #pragma unroll
        for (int r = 0; r < 4; r++) {
            float* base = sm + (g * 4 + r) * ROW_F;
            #pragma unroll
            for (int beh = 0; beh < 3; beh++)
                base[384 + beh * 64 + t] = acc[r][beh] + base[beh * 64 + t];
        }
    }
    __syncthreads();

    if (threadIdx.x < ROWS_PB * 3) {
        int lr  = threadIdx.x / 3;
        int beh = threadIdx.x - lr * 3;
        float* hh = sm + lr * ROW_F + 384 + beh * 64;
        float s = 0.0f;
        #pragma unroll 8
        for (int j = 0; j < 64; j++) s += hh[j];
        float mu = s * (1.0f / 64.0f);
        float v = 0.0f;
        #pragma unroll 8
        for (int j = 0; j < 64; j++) {
            float dd = hh[j] - mu;
            v += dd * dd;
        }
        v *= (1.0f / 64.0f);
        sm[lr * ROW_F + 804 + beh] = mu;
        sm[lr * ROW_F + 808 + beh] = rsqrtf(v + LN_EPS);
    }
    __syncthreads();

    for (int uu = threadIdx.x; uu < ROWS_PB * 64; uu += 128) {
        int lr = uu >> 6;
        int tt = uu & 63;
        float* base = sm + lr * ROW_F;
        float gg = lng[tt], bb = lnb[tt];
        float gsum = 0.0f;
        #pragma unroll
        for (int beh = 0; beh < 3; beh++)
            gsum += (base[384 + beh * 64 + tt] - base[804 + beh]) * base[808 + beh] * gg + bb;
        emb_out[(size_t)(row0 + lr) * 64 + tt] = gsum;
    }
}

// ---------------------------------------------------------------------------
extern "C" void kernel_launch(void* const* d_in, const int* in_sizes, int n_in,
                              void* d_out, int out_size) {
    const float* user_emb = (const float*)d_in[0];
    const float* item_emb = (const float*)d_in[1];
    const float* alpha_w  = (const float*)d_in[2];
    const float* alpha_b  = (const float*)d_in[3];
    const float* wq = (const float*)d_in[4];
    const float* bq = (const float*)d_in[5];
    const float* wk = (const float*)d_in[6];
    const float* bk = (const float*)d_in[7];
    const float* wv = (const float*)d_in[8];
    const float* bv = (const float*)d_in[9];
    const float* wo = (const float*)d_in[10];
    const float* bo = (const float*)d_in[11];
    const float* lng = (const float*)d_in[12];
    const float* lnb = (const float*)d_in[13];
    const int* edge_index = (const int*)d_in[14];
    const int* users      = (const int*)d_in[15];
    const int* pos_items  = (const int*)d_in[16];
    const int* neg_items  = (const int*)d_in[17];

    float* out     = (float*)d_out;
    float* emb_out = out;
    float* tpw     = out + (size_t)3 * BATCH * DIM;
    float* aux     = tpw + (size_t)N_BEH * NE;

    init_kernel<<<256, 256>>>();
    mask_zero_kernel<<<(2 * BATCH * 48 + 255) / 256, 256>>>(pos_items, neg_items);

    edge_act_kernel<<<(size_t)NE_ALL * 4 / 256, 256>>>(user_emb, item_emb,
                                                       alpha_w, alpha_b,
                                                       edge_index, tpw, aux);

    norm_compact_kernel<<<(NE_ALL / 8 + 255) / 256, 256>>>(edge_index, tpw);

    scatter2_kernel<<<4096, 256>>>(user_emb);

    attn_kernel<<<(3 * BATCH) / ROWS_PB, 128>>>(user_emb, item_emb,
                                                wq, bq, wk, bk, wv, bv, wo, bo,
                                                lng, lnb, users, pos_items, neg_items,
                                                emb_out);
}